// round 7
// baseline (speedup 1.0000x reference)
#include <cuda_runtime.h>
#include <math.h>
#include <stdint.h>

#define E 8
#define D 1024
#define NMAX 4096
#define CAP 4096

#define BM 128
#define BN 64
#define KC 32              // K per stage
#define NSTAGE (D / KC)    // 32
#define LDS_PAD 36         // floats per smem row (conflict-free)
#define STG_FLOATS ((BM + BN) * LDS_PAD)   // 6912 floats = 27.65KB per stage
#define SMEM_BYTES (2 * STG_FLOATS * 4)    // 55296 (2-stage ring)

// ---------------- scratch (device globals; no runtime allocation) ----------------
__device__ float g_H[(size_t)E * CAP * D];
__device__ float g_O[(size_t)E * CAP * D];
__device__ float g_xr[(size_t)NMAX * D];       // tf32-rounded x
__device__ float g_W1r[(size_t)E * D * D];     // tf32-rounded w1
__device__ float g_W2r[(size_t)E * D * D];     // tf32-rounded w2
__device__ int   g_cnt[E];
__device__ int   g_tok[E * CAP];
__device__ int   g_slot[NMAX * 2];
__device__ float g_wgt[NMAX * 2];

// ---------------- helpers ----------------
__device__ __forceinline__ uint32_t smem_u32(const void* p) {
    uint32_t a;
    asm("{ .reg .u64 t; cvta.to.shared.u64 t, %1; cvt.u32.u64 %0, t; }" : "=r"(a) : "l"(p));
    return a;
}
__device__ __forceinline__ void cp16(uint32_t s, const void* g) {
    asm volatile("cp.async.cg.shared.global [%0], [%1], 16;" :: "r"(s), "l"(g));
}
__device__ __forceinline__ float round_tf32(float v) {
    uint32_t r;
    asm("cvt.rna.tf32.f32 %0, %1;" : "=r"(r) : "f"(v));
    return __uint_as_float(r);
}
__device__ __forceinline__ void mma_tf32(float* c, const uint32_t* a, const uint32_t* b) {
    asm volatile(
        "mma.sync.aligned.m16n8k8.row.col.f32.tf32.tf32.f32 "
        "{%0,%1,%2,%3}, {%4,%5,%6,%7}, {%8,%9}, {%0,%1,%2,%3};"
        : "+f"(c[0]), "+f"(c[1]), "+f"(c[2]), "+f"(c[3])
        : "r"(a[0]), "r"(a[1]), "r"(a[2]), "r"(a[3]), "r"(b[0]), "r"(b[1]));
}

__global__ void zero_counts_kernel() {
    if (threadIdx.x < E) g_cnt[threadIdx.x] = 0;
}

// ---------------- round weights to tf32 ----------------
__global__ void round_w_kernel(const float* __restrict__ w1,
                               const float* __restrict__ w2)
{
    size_t n = (size_t)E * D * D / 4;
    size_t i = (size_t)blockIdx.x * blockDim.x + threadIdx.x;
    size_t stride = (size_t)gridDim.x * blockDim.x;
    for (; i < n; i += stride) {
        float4 v1 = ((const float4*)w1)[i];
        v1.x = round_tf32(v1.x); v1.y = round_tf32(v1.y);
        v1.z = round_tf32(v1.z); v1.w = round_tf32(v1.w);
        ((float4*)g_W1r)[i] = v1;
        float4 v2 = ((const float4*)w2)[i];
        v2.x = round_tf32(v2.x); v2.y = round_tf32(v2.y);
        v2.z = round_tf32(v2.z); v2.w = round_tf32(v2.w);
        ((float4*)g_W2r)[i] = v2;
    }
}

// ---------------- gating (emits tf32-rounded x) ----------------
__global__ void gate_kernel(const float* __restrict__ x,
                            const float* __restrict__ gW,
                            const float* __restrict__ gb,
                            float* __restrict__ gate_prob_out,
                            int N)
{
    int token = blockIdx.x;
    if (token >= N) return;

    __shared__ float sx[D];
    __shared__ float slog[E];

    const float* xr = x + (size_t)token * D;
    float* xout = g_xr + (size_t)token * D;
    for (int i = threadIdx.x; i < D; i += blockDim.x) {
        float v = xr[i];
        sx[i] = v;
        xout[i] = round_tf32(v);
    }
    __syncthreads();

    int w = threadIdx.x >> 5, lane = threadIdx.x & 31;
    float s = 0.f;
    const float* wr = gW + w * D;
    for (int k = lane; k < D; k += 32) s += sx[k] * wr[k];
    #pragma unroll
    for (int o = 16; o; o >>= 1) s += __shfl_xor_sync(0xffffffffu, s, o);
    if (lane == 0) slog[w] = s + gb[w];
    __syncthreads();

    if (threadIdx.x == 0) {
        float p[E];
        float mx = -1e30f;
        #pragma unroll
        for (int e = 0; e < E; e++) mx = fmaxf(mx, slog[e]);
        float sum = 0.f;
        #pragma unroll
        for (int e = 0; e < E; e++) { p[e] = expf(slog[e] - mx); sum += p[e]; }
        float inv = 1.f / sum;

        int i0 = 0; float p0 = -1.f;
        #pragma unroll
        for (int e = 0; e < E; e++) {
            p[e] *= inv;
            gate_prob_out[(size_t)token * E + e] = p[e];
            if (p[e] > p0) { p0 = p[e]; i0 = e; }
        }
        int i1 = -1; float p1 = -1.f;
        #pragma unroll
        for (int e = 0; e < E; e++)
            if (e != i0 && p[e] > p1) { p1 = p[e]; i1 = e; }

        float e1 = expf(p1 - p0);
        float w0 = 1.f / (1.f + e1);
        float w1 = e1 / (1.f + e1);

        int pos0 = atomicAdd(&g_cnt[i0], 1);
        int pos1 = atomicAdd(&g_cnt[i1], 1);
        g_tok[i0 * CAP + pos0] = token;
        g_tok[i1 * CAP + pos1] = token;
        g_slot[token * 2 + 0] = i0 * CAP + pos0;
        g_slot[token * 2 + 1] = i1 * CAP + pos1;
        g_wgt[token * 2 + 0] = w0;
        g_wgt[token * 2 + 1] = w1;
    }
}

// ---------------- expert GEMM: 128x64 CTA tile, 8 warps of 32x32, 3 CTAs/SM ----------------
// mode 0: A = gathered g_xr rows, W = g_W1r -> g_H (relu, b1, tf32-rounded store)
// mode 1: A = g_H rows,           W = g_W2r -> g_O (b2, full fp32 store)
__global__ __launch_bounds__(256, 3)
void expert_gemm_mma(const float* __restrict__ bias, int mode)
{
    int e  = blockIdx.z;
    int ne = g_cnt[e];
    int m0 = blockIdx.x * BM;
    if (m0 >= ne) return;
    int n0 = blockIdx.y * BN;

    extern __shared__ float sm[];
    uint32_t smb = smem_u32(sm);

    int tid = threadIdx.x;

    const float* W = (mode == 0) ? g_W1r : g_W2r;

    // A loader: thread t -> row t>>1 (0..127), half t&1 (16 floats = 4 cp16)
    int arow = tid >> 1, ahalf = tid & 1;
    const float* Aptr;
    if (mode == 0) {
        int tok = (m0 + arow < ne) ? g_tok[e * CAP + m0 + arow] : 0;
        Aptr = g_xr + (size_t)tok * D + ahalf * 16;
    } else {
        Aptr = g_H + ((size_t)e * CAP + m0 + arow) * D + ahalf * 16;
    }
    uint32_t a_sm = smb + (uint32_t)(arow * LDS_PAD + ahalf * 16) * 4u;

    // B loader: thread t -> row t>>2 (0..63), quarter t&3 (8 floats = 2 cp16)
    int brow = tid >> 2, bq = tid & 3;
    const float* Bptr = W + ((size_t)e * D + n0 + brow) * D + bq * 8;
    uint32_t b_sm = smb + (uint32_t)(BM * LDS_PAD + brow * LDS_PAD + bq * 8) * 4u;

    #define LOAD_STAGE(buf, k0) do {                                      \
        uint32_t _off = (uint32_t)(buf) * (STG_FLOATS * 4);                \
        const float* _ag = Aptr + (k0);                                    \
        const float* _bg = Bptr + (k0);                                    \
        cp16(a_sm + _off,      _ag);                                       \
        cp16(a_sm + _off + 16, _ag + 4);                                   \
        cp16(a_sm + _off + 32, _ag + 8);                                   \
        cp16(a_sm + _off + 48, _ag + 12);                                  \
        cp16(b_sm + _off,      _bg);                                       \
        cp16(b_sm + _off + 16, _bg + 4);                                   \
        asm volatile("cp.async.commit_group;" ::: "memory");               \
    } while (0)

    LOAD_STAGE(0, 0);

    int wid = tid >> 5, lane = tid & 31;
    int g  = lane >> 2, tg = lane & 3;
    int wm = (wid >> 1) * 32;       // 4 warps in m
    int wn = (wid & 1) * 32;        // 2 warps in n

    float acc[2][4][4];
    #pragma unroll
    for (int mt = 0; mt < 2; mt++)
        #pragma unroll
        for (int nt = 0; nt < 4; nt++)
            #pragma unroll
            for (int i = 0; i < 4; i++) acc[mt][nt][i] = 0.f;

    #pragma unroll 1
    for (int s = 0; s < NSTAGE; s++) {
        // buffer (s+1)%2 was fully consumed at end of iteration s-1
        __syncthreads();
        if (s + 1 < NSTAGE) {
            LOAD_STAGE((s + 1) & 1, (s + 1) * KC);
            asm volatile("cp.async.wait_group 1;" ::: "memory");  // stage s complete
        } else {
            asm volatile("cp.async.wait_group 0;" ::: "memory");
        }
        __syncthreads();   // stage s visible to all warps

        const float* As = sm + (s & 1) * STG_FLOATS;
        const float* Bs = As + BM * LDS_PAD;

        #pragma unroll
        for (int kk = 0; kk < 4; kk++) {
            uint32_t a[2][4], b[4][2];
            #pragma unroll
            for (int mt = 0; mt < 2; mt++) {
                const uint32_t* ap = (const uint32_t*)(As + (wm + mt * 16 + g) * LDS_PAD + kk * 8 + tg);
                a[mt][0] = ap[0];
                a[mt][1] = ap[8 * LDS_PAD];
                a[mt][2] = ap[4];
                a[mt][3] = ap[8 * LDS_PAD + 4];
            }
            #pragma unroll
            for (int nt = 0; nt < 4; nt++) {
                const uint32_t* bp = (const uint32_t*)(Bs + (wn + nt * 8 + g) * LDS_PAD + kk * 8 + tg);
                b[nt][0] = bp[0];
                b[nt][1] = bp[4];
            }
            #pragma unroll
            for (int mt = 0; mt < 2; mt++)
                #pragma unroll
                for (int nt = 0; nt < 4; nt++)
                    mma_tf32(acc[mt][nt], a[mt], b[nt]);
        }
    }

    // ---------------- epilogue ----------------
    const float* brw = bias + (size_t)e * D + n0;
    float* Cb = (mode == 0) ? g_H : g_O;

    #pragma unroll
    for (int mt = 0; mt < 2; mt++) {
        #pragma unroll
        for (int rr = 0; rr < 2; rr++) {
            int m = m0 + wm + mt * 16 + rr * 8 + g;
            if (m >= ne) continue;
            float* crow = Cb + ((size_t)e * CAP + m) * D + n0;
            #pragma unroll
            for (int nt = 0; nt < 4; nt++) {
                int col = wn + nt * 8 + tg * 2;
                float v0 = acc[mt][nt][rr * 2 + 0] + brw[col];
                float v1 = acc[mt][nt][rr * 2 + 1] + brw[col + 1];
                if (mode == 0) {
                    v0 = round_tf32(fmaxf(v0, 0.f));   // pre-round H for pass 2
                    v1 = round_tf32(fmaxf(v1, 0.f));
                }
                float2 v = make_float2(v0, v1);
                *(float2*)(crow + col) = v;
            }
        }
    }
}

// ---------------- combine ----------------
__global__ void combine_kernel(float* __restrict__ y, int N)
{
    int token = blockIdx.x;
    if (token >= N) return;
    int   s0 = g_slot[token * 2 + 0];
    int   s1 = g_slot[token * 2 + 1];
    float w0 = g_wgt[token * 2 + 0];
    float w1 = g_wgt[token * 2 + 1];
    const float* o0 = g_O + (size_t)s0 * D;
    const float* o1 = g_O + (size_t)s1 * D;
    float* yr = y + (size_t)token * D;
    for (int i = threadIdx.x; i < D; i += blockDim.x)
        yr[i] = w0 * o0[i] + w1 * o1[i];
}

extern "C" void kernel_launch(void* const* d_in, const int* in_sizes, int n_in,
                              void* d_out, int out_size)
{
    const float* x  = (const float*)d_in[0];
    const float* gW = (const float*)d_in[1];
    const float* gb = (const float*)d_in[2];
    const float* w1 = (const float*)d_in[3];
    const float* b1 = (const float*)d_in[4];
    const float* w2 = (const float*)d_in[5];
    const float* b2 = (const float*)d_in[6];

    int N = in_sizes[0] / D;   // 4096

    float* y         = (float*)d_out;
    float* gate_prob = (float*)d_out + (size_t)N * D;

    static int smem_set = 0;
    if (!smem_set) {
        cudaFuncSetAttribute(expert_gemm_mma,
                             cudaFuncAttributeMaxDynamicSharedMemorySize, SMEM_BYTES);
        smem_set = 1;
    }

    zero_counts_kernel<<<1, 32>>>();
    round_w_kernel<<<1184, 256>>>(w1, w2);
    gate_kernel<<<N, 256>>>(x, gW, gb, gate_prob, N);

    dim3 grid(NMAX / BM, D / BN, E);   // 32 x 16 x 8, inactive tiles exit early
    expert_gemm_mma<<<grid, 256, SMEM_BYTES>>>(b1, 0);
    expert_gemm_mma<<<grid, 256, SMEM_BYTES>>>(b2, 1);

    combine_kernel<<<N, 256>>>(y, N);
}

// round 8
// speedup vs baseline: 1.8117x; 1.8117x over previous
#include <cuda_runtime.h>
#include <cuda_fp16.h>
#include <math.h>
#include <stdint.h>

#define E 8
#define D 1024
#define NMAX 4096
#define CAP 4096

#define BM 128
#define BN 128
#define KCH 64                 // halfs of K per stage
#define NSTAGE (D / KCH)       // 16
#define ROWPAD 72              // halfs per smem row (144B = 9*16B: aligned + ldmatrix conflict-free)
#define STG_BYTES ((BM + BN) * ROWPAD * 2)   // 36864
#define SMEM_BYTES (3 * STG_BYTES)           // 110592

// ---------------- scratch (device globals; no runtime allocation) ----------------
__device__ __half g_Hh[(size_t)E * CAP * D];   // hidden activations (fp16)
__device__ float  g_O[(size_t)E * CAP * D];    // expert outputs (fp32)
__device__ __half g_xh[(size_t)NMAX * D];      // fp16 x
__device__ __half g_W1h[(size_t)E * D * D];    // fp16 w1
__device__ __half g_W2h[(size_t)E * D * D];    // fp16 w2
__device__ int    g_cnt[E];
__device__ int    g_tok[E * CAP];
__device__ int    g_slot[NMAX * 2];
__device__ float  g_wgt[NMAX * 2];

// ---------------- helpers ----------------
__device__ __forceinline__ uint32_t smem_u32(const void* p) {
    uint32_t a;
    asm("{ .reg .u64 t; cvta.to.shared.u64 t, %1; cvt.u32.u64 %0, t; }" : "=r"(a) : "l"(p));
    return a;
}
__device__ __forceinline__ void cp16(uint32_t s, const void* g) {
    asm volatile("cp.async.cg.shared.global [%0], [%1], 16;" :: "r"(s), "l"(g));
}
__device__ __forceinline__ void ldsm4(uint32_t& r0, uint32_t& r1, uint32_t& r2, uint32_t& r3,
                                      uint32_t addr) {
    asm volatile("ldmatrix.sync.aligned.m8n8.x4.shared.b16 {%0,%1,%2,%3}, [%4];"
                 : "=r"(r0), "=r"(r1), "=r"(r2), "=r"(r3) : "r"(addr));
}
__device__ __forceinline__ void mma_f16(float* c, const uint32_t* a, uint32_t b0, uint32_t b1) {
    asm volatile(
        "mma.sync.aligned.m16n8k16.row.col.f32.f16.f16.f32 "
        "{%0,%1,%2,%3}, {%4,%5,%6,%7}, {%8,%9}, {%0,%1,%2,%3};"
        : "+f"(c[0]), "+f"(c[1]), "+f"(c[2]), "+f"(c[3])
        : "r"(a[0]), "r"(a[1]), "r"(a[2]), "r"(a[3]), "r"(b0), "r"(b1));
}

__global__ void zero_counts_kernel() {
    if (threadIdx.x < E) g_cnt[threadIdx.x] = 0;
}

// ---------------- convert weights to fp16 ----------------
__global__ void convert_w_kernel(const float* __restrict__ w1,
                                 const float* __restrict__ w2)
{
    size_t n = (size_t)E * D * D / 4;     // float4 count
    size_t i = (size_t)blockIdx.x * blockDim.x + threadIdx.x;
    size_t stride = (size_t)gridDim.x * blockDim.x;
    for (; i < n; i += stride) {
        float4 v1 = ((const float4*)w1)[i];
        __half2* o1 = (__half2*)g_W1h + i * 2;
        o1[0] = __floats2half2_rn(v1.x, v1.y);
        o1[1] = __floats2half2_rn(v1.z, v1.w);
        float4 v2 = ((const float4*)w2)[i];
        __half2* o2 = (__half2*)g_W2h + i * 2;
        o2[0] = __floats2half2_rn(v2.x, v2.y);
        o2[1] = __floats2half2_rn(v2.z, v2.w);
    }
}

// ---------------- gating (emits fp16 x) ----------------
__global__ void gate_kernel(const float* __restrict__ x,
                            const float* __restrict__ gW,
                            const float* __restrict__ gb,
                            float* __restrict__ gate_prob_out,
                            int N)
{
    int token = blockIdx.x;
    if (token >= N) return;

    __shared__ float sx[D];
    __shared__ float slog[E];

    const float* xr = x + (size_t)token * D;
    __half* xout = g_xh + (size_t)token * D;
    for (int i = threadIdx.x; i < D; i += blockDim.x) {
        float v = xr[i];
        sx[i] = v;
        xout[i] = __float2half_rn(v);
    }
    __syncthreads();

    int w = threadIdx.x >> 5, lane = threadIdx.x & 31;
    float s = 0.f;
    const float* wr = gW + w * D;
    for (int k = lane; k < D; k += 32) s += sx[k] * wr[k];
    #pragma unroll
    for (int o = 16; o; o >>= 1) s += __shfl_xor_sync(0xffffffffu, s, o);
    if (lane == 0) slog[w] = s + gb[w];
    __syncthreads();

    if (threadIdx.x == 0) {
        float p[E];
        float mx = -1e30f;
        #pragma unroll
        for (int e = 0; e < E; e++) mx = fmaxf(mx, slog[e]);
        float sum = 0.f;
        #pragma unroll
        for (int e = 0; e < E; e++) { p[e] = expf(slog[e] - mx); sum += p[e]; }
        float inv = 1.f / sum;

        int i0 = 0; float p0 = -1.f;
        #pragma unroll
        for (int e = 0; e < E; e++) {
            p[e] *= inv;
            gate_prob_out[(size_t)token * E + e] = p[e];
            if (p[e] > p0) { p0 = p[e]; i0 = e; }
        }
        int i1 = -1; float p1 = -1.f;
        #pragma unroll
        for (int e = 0; e < E; e++)
            if (e != i0 && p[e] > p1) { p1 = p[e]; i1 = e; }

        float e1 = expf(p1 - p0);
        float w0 = 1.f / (1.f + e1);
        float w1 = e1 / (1.f + e1);

        int pos0 = atomicAdd(&g_cnt[i0], 1);
        int pos1 = atomicAdd(&g_cnt[i1], 1);
        g_tok[i0 * CAP + pos0] = token;
        g_tok[i1 * CAP + pos1] = token;
        g_slot[token * 2 + 0] = i0 * CAP + pos0;
        g_slot[token * 2 + 1] = i1 * CAP + pos1;
        g_wgt[token * 2 + 0] = w0;
        g_wgt[token * 2 + 1] = w1;
    }
}

// ---------------- expert GEMM: fp16 mma.m16n8k16 + ldmatrix ----------------
// 128x128 CTA tile, 4 warps of 64x64, 3-stage cp.async ring, 2 CTAs/SM.
// mode 0: A = gathered g_xh rows, W = g_W1h -> g_Hh (relu + b1, half store)
// mode 1: A = g_Hh rows,          W = g_W2h -> g_O  (b2, float store)
__global__ __launch_bounds__(128, 2)
void expert_gemm_mma(const float* __restrict__ bias, int mode)
{
    int e  = blockIdx.z;
    int ne = g_cnt[e];
    int m0 = blockIdx.x * BM;
    if (m0 >= ne) return;
    int n0 = blockIdx.y * BN;

    extern __shared__ char sm[];
    uint32_t smb = smem_u32(sm);

    int tid = threadIdx.x;   // 0..127

    const __half* W = (mode == 0) ? g_W1h : g_W2h;

    // loaders: thread t owns A row t and B row t (128B = 8 cp16 each per stage)
    const __half* Aptr;
    if (mode == 0) {
        int tok = (m0 + tid < ne) ? g_tok[e * CAP + m0 + tid] : 0;
        Aptr = g_xh + (size_t)tok * D;
    } else {
        Aptr = g_Hh + ((size_t)e * CAP + m0 + tid) * D;
    }
    const __half* Bptr = W + ((size_t)e * D + n0 + tid) * D;

    uint32_t a_sm = smb + (uint32_t)tid * (ROWPAD * 2);
    uint32_t b_sm = smb + (uint32_t)(BM + tid) * (ROWPAD * 2);

    #define LOAD_STAGE(buf, k0) do {                                       \
        uint32_t _off = (uint32_t)(buf) * STG_BYTES;                        \
        const __half* _ag = Aptr + (k0);                                    \
        const __half* _bg = Bptr + (k0);                                    \
        _Pragma("unroll")                                                   \
        for (int _c = 0; _c < 8; _c++) {                                    \
            cp16(a_sm + _off + _c * 16u, _ag + _c * 8);                     \
            cp16(b_sm + _off + _c * 16u, _bg + _c * 8);                     \
        }                                                                   \
        asm volatile("cp.async.commit_group;" ::: "memory");                \
    } while (0)

    LOAD_STAGE(0, 0);
    LOAD_STAGE(1, KCH);

    int wid = tid >> 5, lane = tid & 31;
    int g  = lane >> 2, tg = lane & 3;
    int wm = (wid >> 1) * 64;       // 2 warps in m
    int wn = (wid & 1) * 64;        // 2 warps in n

    // per-lane ldmatrix offsets within a stage (bytes)
    uint32_t a_off[4], b_off[4];
    #pragma unroll
    for (int mt = 0; mt < 4; mt++) {
        int row = wm + mt * 16 + (lane & 15);
        a_off[mt] = (uint32_t)(row * ROWPAD + (lane >> 4) * 8) * 2u;
    }
    #pragma unroll
    for (int nt2 = 0; nt2 < 4; nt2++) {
        int row = wn + nt2 * 16 + (lane & 7) + ((lane >> 4) & 1) * 8;
        b_off[nt2] = (uint32_t)((BM + row) * ROWPAD + ((lane >> 3) & 1) * 8) * 2u;
    }

    float acc[4][8][4];
    #pragma unroll
    for (int mt = 0; mt < 4; mt++)
        #pragma unroll
        for (int nt = 0; nt < 8; nt++)
            #pragma unroll
            for (int i = 0; i < 4; i++) acc[mt][nt][i] = 0.f;

    #pragma unroll 1
    for (int s = 0; s < NSTAGE; s++) {
        if (s < NSTAGE - 1) asm volatile("cp.async.wait_group 1;" ::: "memory");
        else                asm volatile("cp.async.wait_group 0;" ::: "memory");
        __syncthreads();

        if (s + 2 < NSTAGE) LOAD_STAGE((s + 2) % 3, (s + 2) * KCH);

        uint32_t stg = smb + (uint32_t)(s % 3) * STG_BYTES;

        #pragma unroll
        for (int kk = 0; kk < KCH / 16; kk++) {
            uint32_t koff = (uint32_t)kk * 32u;   // 16 halfs
            uint32_t a[4][4], b[4][4];
            #pragma unroll
            for (int mt = 0; mt < 4; mt++)
                ldsm4(a[mt][0], a[mt][1], a[mt][2], a[mt][3], stg + a_off[mt] + koff);
            #pragma unroll
            for (int nt2 = 0; nt2 < 4; nt2++)
                ldsm4(b[nt2][0], b[nt2][1], b[nt2][2], b[nt2][3], stg + b_off[nt2] + koff);
            #pragma unroll
            for (int mt = 0; mt < 4; mt++)
                #pragma unroll
                for (int nt = 0; nt < 8; nt++)
                    mma_f16(acc[mt][nt], a[mt], b[nt >> 1][(nt & 1) * 2], b[nt >> 1][(nt & 1) * 2 + 1]);
        }
    }

    // ---------------- epilogue ----------------
    const float* brw = bias + (size_t)e * D + n0;

    #pragma unroll
    for (int mt = 0; mt < 4; mt++) {
        #pragma unroll
        for (int rr = 0; rr < 2; rr++) {
            int m = m0 + wm + mt * 16 + rr * 8 + g;
            if (m >= ne) continue;
            size_t rowbase = ((size_t)e * CAP + m) * D + n0;
            #pragma unroll
            for (int nt = 0; nt < 8; nt++) {
                int col = wn + nt * 8 + tg * 2;
                float v0 = acc[mt][nt][rr * 2 + 0] + brw[col];
                float v1 = acc[mt][nt][rr * 2 + 1] + brw[col + 1];
                if (mode == 0) {
                    v0 = fmaxf(v0, 0.f);
                    v1 = fmaxf(v1, 0.f);
                    *(__half2*)(g_Hh + rowbase + col) = __floats2half2_rn(v0, v1);
                } else {
                    *(float2*)(g_O + rowbase + col) = make_float2(v0, v1);
                }
            }
        }
    }
}

// ---------------- combine ----------------
__global__ void combine_kernel(float* __restrict__ y, int N)
{
    int token = blockIdx.x;
    if (token >= N) return;
    int   s0 = g_slot[token * 2 + 0];
    int   s1 = g_slot[token * 2 + 1];
    float w0 = g_wgt[token * 2 + 0];
    float w1 = g_wgt[token * 2 + 1];
    const float* o0 = g_O + (size_t)s0 * D;
    const float* o1 = g_O + (size_t)s1 * D;
    float* yr = y + (size_t)token * D;
    for (int i = threadIdx.x; i < D; i += blockDim.x)
        yr[i] = w0 * o0[i] + w1 * o1[i];
}

extern "C" void kernel_launch(void* const* d_in, const int* in_sizes, int n_in,
                              void* d_out, int out_size)
{
    const float* x  = (const float*)d_in[0];
    const float* gW = (const float*)d_in[1];
    const float* gb = (const float*)d_in[2];
    const float* w1 = (const float*)d_in[3];
    const float* b1 = (const float*)d_in[4];
    const float* w2 = (const float*)d_in[5];
    const float* b2 = (const float*)d_in[6];

    int N = in_sizes[0] / D;   // 4096

    float* y         = (float*)d_out;
    float* gate_prob = (float*)d_out + (size_t)N * D;

    static int smem_set = 0;
    if (!smem_set) {
        cudaFuncSetAttribute(expert_gemm_mma,
                             cudaFuncAttributeMaxDynamicSharedMemorySize, SMEM_BYTES);
        smem_set = 1;
    }

    zero_counts_kernel<<<1, 32>>>();
    convert_w_kernel<<<1184, 256>>>(w1, w2);
    gate_kernel<<<N, 256>>>(x, gW, gb, gate_prob, N);

    dim3 grid(NMAX / BM, D / BN, E);   // 32 x 8 x 8, inactive tiles exit early
    expert_gemm_mma<<<grid, 128, SMEM_BYTES>>>(b1, 0);
    expert_gemm_mma<<<grid, 128, SMEM_BYTES>>>(b2, 1);

    combine_kernel<<<N, 256>>>(y, N);
}

// round 9
// speedup vs baseline: 1.8188x; 1.0039x over previous
#include <cuda_runtime.h>
#include <cuda_fp16.h>
#include <math.h>
#include <stdint.h>

#define E 8
#define D 1024
#define NMAX 4096
#define CAP 4096

#define BM 128
#define BN 128
#define KCH 64                 // halfs of K per stage
#define NSTAGE (D / KCH)       // 16
#define ROWPAD 72              // halfs per smem row (144B = 9*16B)
#define STG_BYTES ((BM + BN) * ROWPAD * 2)   // 36864
#define SMEM_BYTES (3 * STG_BYTES)           // 110592

// ---------------- scratch (device globals; no runtime allocation) ----------------
__device__ __half g_Hh[(size_t)E * CAP * D];
__device__ float  g_O[(size_t)E * CAP * D];
__device__ __half g_xh[(size_t)NMAX * D];
__device__ __half g_W1h[(size_t)E * D * D];
__device__ __half g_W2h[(size_t)E * D * D];
__device__ int    g_cnt[E];
__device__ int    g_tok[E * CAP];
__device__ int    g_slot[NMAX * 2];
__device__ float  g_wgt[NMAX * 2];

// ---------------- helpers ----------------
__device__ __forceinline__ uint32_t smem_u32(const void* p) {
    uint32_t a;
    asm("{ .reg .u64 t; cvta.to.shared.u64 t, %1; cvt.u32.u64 %0, t; }" : "=r"(a) : "l"(p));
    return a;
}
__device__ __forceinline__ void cp16(uint32_t s, const void* g) {
    asm volatile("cp.async.cg.shared.global [%0], [%1], 16;" :: "r"(s), "l"(g));
}
__device__ __forceinline__ void ldsm4(uint32_t& r0, uint32_t& r1, uint32_t& r2, uint32_t& r3,
                                      uint32_t addr) {
    asm volatile("ldmatrix.sync.aligned.m8n8.x4.shared.b16 {%0,%1,%2,%3}, [%4];"
                 : "=r"(r0), "=r"(r1), "=r"(r2), "=r"(r3) : "r"(addr));
}
__device__ __forceinline__ void mma_f16(float* c, const uint32_t* a, uint32_t b0, uint32_t b1) {
    asm volatile(
        "mma.sync.aligned.m16n8k16.row.col.f32.f16.f16.f32 "
        "{%0,%1,%2,%3}, {%4,%5,%6,%7}, {%8,%9}, {%0,%1,%2,%3};"
        : "+f"(c[0]), "+f"(c[1]), "+f"(c[2]), "+f"(c[3])
        : "r"(a[0]), "r"(a[1]), "r"(a[2]), "r"(a[3]), "r"(b0), "r"(b1));
}

__global__ void zero_counts_kernel() {
    if (threadIdx.x < E) g_cnt[threadIdx.x] = 0;
}

// ---------------- convert weights to fp16 ----------------
__global__ void convert_w_kernel(const float* __restrict__ w1,
                                 const float* __restrict__ w2)
{
    size_t n = (size_t)E * D * D / 4;
    size_t i = (size_t)blockIdx.x * blockDim.x + threadIdx.x;
    size_t stride = (size_t)gridDim.x * blockDim.x;
    for (; i < n; i += stride) {
        float4 v1 = ((const float4*)w1)[i];
        __half2* o1 = (__half2*)g_W1h + i * 2;
        o1[0] = __floats2half2_rn(v1.x, v1.y);
        o1[1] = __floats2half2_rn(v1.z, v1.w);
        float4 v2 = ((const float4*)w2)[i];
        __half2* o2 = (__half2*)g_W2h + i * 2;
        o2[0] = __floats2half2_rn(v2.x, v2.y);
        o2[1] = __floats2half2_rn(v2.z, v2.w);
    }
}

// ---------------- gating (emits fp16 x) ----------------
__global__ void gate_kernel(const float* __restrict__ x,
                            const float* __restrict__ gW,
                            const float* __restrict__ gb,
                            float* __restrict__ gate_prob_out,
                            int N)
{
    int token = blockIdx.x;
    if (token >= N) return;

    __shared__ float sx[D];
    __shared__ float slog[E];

    const float* xr = x + (size_t)token * D;
    __half* xout = g_xh + (size_t)token * D;
    for (int i = threadIdx.x; i < D; i += blockDim.x) {
        float v = xr[i];
        sx[i] = v;
        xout[i] = __float2half_rn(v);
    }
    __syncthreads();

    int w = threadIdx.x >> 5, lane = threadIdx.x & 31;
    float s = 0.f;
    const float* wr = gW + w * D;
    for (int k = lane; k < D; k += 32) s += sx[k] * wr[k];
    #pragma unroll
    for (int o = 16; o; o >>= 1) s += __shfl_xor_sync(0xffffffffu, s, o);
    if (lane == 0) slog[w] = s + gb[w];
    __syncthreads();

    if (threadIdx.x == 0) {
        float p[E];
        float mx = -1e30f;
        #pragma unroll
        for (int e = 0; e < E; e++) mx = fmaxf(mx, slog[e]);
        float sum = 0.f;
        #pragma unroll
        for (int e = 0; e < E; e++) { p[e] = expf(slog[e] - mx); sum += p[e]; }
        float inv = 1.f / sum;

        int i0 = 0; float p0 = -1.f;
        #pragma unroll
        for (int e = 0; e < E; e++) {
            p[e] *= inv;
            gate_prob_out[(size_t)token * E + e] = p[e];
            if (p[e] > p0) { p0 = p[e]; i0 = e; }
        }
        int i1 = -1; float p1 = -1.f;
        #pragma unroll
        for (int e = 0; e < E; e++)
            if (e != i0 && p[e] > p1) { p1 = p[e]; i1 = e; }

        float e1 = expf(p1 - p0);
        float w0 = 1.f / (1.f + e1);
        float w1 = e1 / (1.f + e1);

        int pos0 = atomicAdd(&g_cnt[i0], 1);
        int pos1 = atomicAdd(&g_cnt[i1], 1);
        g_tok[i0 * CAP + pos0] = token;
        g_tok[i1 * CAP + pos1] = token;
        g_slot[token * 2 + 0] = i0 * CAP + pos0;
        g_slot[token * 2 + 1] = i1 * CAP + pos1;
        g_wgt[token * 2 + 0] = w0;
        g_wgt[token * 2 + 1] = w1;
    }
}

// ---------------- expert GEMM: fp16 mma + ldmatrix, 8 warps of 64x32 ----------------
// mode 0: A = gathered g_xh rows, W = g_W1h -> g_Hh (relu + b1, half store)
// mode 1: A = g_Hh rows,          W = g_W2h -> g_O  (b2, float store)
__global__ __launch_bounds__(256, 2)
void expert_gemm_mma(const float* __restrict__ bias, int mode)
{
    int e  = blockIdx.z;
    int ne = g_cnt[e];
    int m0 = blockIdx.x * BM;
    if (m0 >= ne) return;
    int n0 = blockIdx.y * BN;

    extern __shared__ char sm[];
    uint32_t smb = smem_u32(sm);

    int tid = threadIdx.x;   // 0..255

    const __half* W = (mode == 0) ? g_W1h : g_W2h;

    // loader: threads 0..127 own A row tid; threads 128..255 own B row tid-128
    const __half* Rptr;
    if (tid < BM) {
        if (mode == 0) {
            int tok = (m0 + tid < ne) ? g_tok[e * CAP + m0 + tid] : 0;
            Rptr = g_xh + (size_t)tok * D;
        } else {
            Rptr = g_Hh + ((size_t)e * CAP + m0 + tid) * D;
        }
    } else {
        Rptr = W + ((size_t)e * D + n0 + (tid - BM)) * D;
    }
    uint32_t r_sm = smb + (uint32_t)tid * (ROWPAD * 2);

    #define LOAD_STAGE(buf, k0) do {                                       \
        uint32_t _off = (uint32_t)(buf) * STG_BYTES;                        \
        const __half* _rg = Rptr + (k0);                                    \
        _Pragma("unroll")                                                   \
        for (int _c = 0; _c < 8; _c++)                                      \
            cp16(r_sm + _off + _c * 16u, _rg + _c * 8);                     \
        asm volatile("cp.async.commit_group;" ::: "memory");                \
    } while (0)

    LOAD_STAGE(0, 0);
    LOAD_STAGE(1, KCH);

    int wid = tid >> 5, lane = tid & 31;
    int g  = lane >> 2, tg = lane & 3;
    int wm = (wid >> 2) * 64;       // 2 warps in m (64 rows each)
    int wn = (wid & 3) * 32;        // 4 warps in n (32 cols each)

    // ldmatrix offsets (bytes within a stage)
    uint32_t a_off[4], b_off[2];
    #pragma unroll
    for (int mt = 0; mt < 4; mt++) {
        int row = wm + mt * 16 + (lane & 15);
        a_off[mt] = (uint32_t)(row * ROWPAD + (lane >> 4) * 8) * 2u;
    }
    #pragma unroll
    for (int nt2 = 0; nt2 < 2; nt2++) {
        int row = wn + nt2 * 16 + (lane & 7) + ((lane >> 4) & 1) * 8;
        b_off[nt2] = (uint32_t)((BM + row) * ROWPAD + ((lane >> 3) & 1) * 8) * 2u;
    }

    float acc[4][4][4];
    #pragma unroll
    for (int mt = 0; mt < 4; mt++)
        #pragma unroll
        for (int nt = 0; nt < 4; nt++)
            #pragma unroll
            for (int i = 0; i < 4; i++) acc[mt][nt][i] = 0.f;

    #pragma unroll 1
    for (int s = 0; s < NSTAGE; s++) {
        if (s < NSTAGE - 1) asm volatile("cp.async.wait_group 1;" ::: "memory");
        else                asm volatile("cp.async.wait_group 0;" ::: "memory");
        __syncthreads();

        if (s + 2 < NSTAGE) LOAD_STAGE((s + 2) % 3, (s + 2) * KCH);

        uint32_t stg = smb + (uint32_t)(s % 3) * STG_BYTES;

        #pragma unroll
        for (int kk = 0; kk < KCH / 16; kk++) {
            uint32_t koff = (uint32_t)kk * 32u;   // 16 halfs
            uint32_t a[4][4], b[2][4];
            #pragma unroll
            for (int mt = 0; mt < 4; mt++)
                ldsm4(a[mt][0], a[mt][1], a[mt][2], a[mt][3], stg + a_off[mt] + koff);
            #pragma unroll
            for (int nt2 = 0; nt2 < 2; nt2++)
                ldsm4(b[nt2][0], b[nt2][1], b[nt2][2], b[nt2][3], stg + b_off[nt2] + koff);
            #pragma unroll
            for (int mt = 0; mt < 4; mt++)
                #pragma unroll
                for (int nt = 0; nt < 4; nt++)
                    mma_f16(acc[mt][nt], a[mt], b[nt >> 1][(nt & 1) * 2], b[nt >> 1][(nt & 1) * 2 + 1]);
        }
    }

    // ---------------- epilogue ----------------
    const float* brw = bias + (size_t)e * D + n0;

    #pragma unroll
    for (int mt = 0; mt < 4; mt++) {
        #pragma unroll
        for (int rr = 0; rr < 2; rr++) {
            int m = m0 + wm + mt * 16 + rr * 8 + g;
            if (m >= ne) continue;
            size_t rowbase = ((size_t)e * CAP + m) * D + n0;
            #pragma unroll
            for (int nt = 0; nt < 4; nt++) {
                int col = wn + nt * 8 + tg * 2;
                float v0 = acc[mt][nt][rr * 2 + 0] + brw[col];
                float v1 = acc[mt][nt][rr * 2 + 1] + brw[col + 1];
                if (mode == 0) {
                    v0 = fmaxf(v0, 0.f);
                    v1 = fmaxf(v1, 0.f);
                    *(__half2*)(g_Hh + rowbase + col) = __floats2half2_rn(v0, v1);
                } else {
                    *(float2*)(g_O + rowbase + col) = make_float2(v0, v1);
                }
            }
        }
    }
}

// ---------------- combine ----------------
__global__ void combine_kernel(float* __restrict__ y, int N)
{
    int token = blockIdx.x;
    if (token >= N) return;
    int   s0 = g_slot[token * 2 + 0];
    int   s1 = g_slot[token * 2 + 1];
    float w0 = g_wgt[token * 2 + 0];
    float w1 = g_wgt[token * 2 + 1];
    const float* o0 = g_O + (size_t)s0 * D;
    const float* o1 = g_O + (size_t)s1 * D;
    float* yr = y + (size_t)token * D;
    for (int i = threadIdx.x; i < D; i += blockDim.x)
        yr[i] = w0 * o0[i] + w1 * o1[i];
}

extern "C" void kernel_launch(void* const* d_in, const int* in_sizes, int n_in,
                              void* d_out, int out_size)
{
    const float* x  = (const float*)d_in[0];
    const float* gW = (const float*)d_in[1];
    const float* gb = (const float*)d_in[2];
    const float* w1 = (const float*)d_in[3];
    const float* b1 = (const float*)d_in[4];
    const float* w2 = (const float*)d_in[5];
    const float* b2 = (const float*)d_in[6];

    int N = in_sizes[0] / D;   // 4096

    float* y         = (float*)d_out;
    float* gate_prob = (float*)d_out + (size_t)N * D;

    static int smem_set = 0;
    if (!smem_set) {
        cudaFuncSetAttribute(expert_gemm_mma,
                             cudaFuncAttributeMaxDynamicSharedMemorySize, SMEM_BYTES);
        smem_set = 1;
    }

    zero_counts_kernel<<<1, 32>>>();
    convert_w_kernel<<<1184, 256>>>(w1, w2);
    gate_kernel<<<N, 256>>>(x, gW, gb, gate_prob, N);

    dim3 grid(NMAX / BM, D / BN, E);   // 32 x 8 x 8, inactive tiles exit early
    expert_gemm_mma<<<grid, 256, SMEM_BYTES>>>(b1, 0);
    expert_gemm_mma<<<grid, 256, SMEM_BYTES>>>(b2, 1);

    combine_kernel<<<N, 256>>>(y, N);
}

// round 10
// speedup vs baseline: 1.9692x; 1.0827x over previous
#include <cuda_runtime.h>
#include <cuda_fp16.h>
#include <math.h>
#include <stdint.h>

#define E 8
#define D 1024
#define NMAX 4096
#define CAP 4096

#define BM 128
#define BN 256
#define KCH 64                 // halfs of K per stage
#define NSTAGE (D / KCH)       // 16
#define ROWPAD 72              // halfs per smem row (144B = 9*16B)
#define STG_BYTES ((BM + BN) * ROWPAD * 2)   // 55296
#define SMEM_BYTES (3 * STG_BYTES)           // 165888

// ---------------- scratch (device globals; no runtime allocation) ----------------
__device__ __half g_Hh[(size_t)E * CAP * D];
__device__ float  g_O[(size_t)E * CAP * D];
__device__ __half g_xh[(size_t)NMAX * D];
__device__ __half g_W1h[(size_t)E * D * D];
__device__ __half g_W2h[(size_t)E * D * D];
__device__ int    g_cnt[E];
__device__ int    g_tok[E * CAP];
__device__ int    g_slot[NMAX * 2];
__device__ float  g_wgt[NMAX * 2];

// ---------------- helpers ----------------
__device__ __forceinline__ uint32_t smem_u32(const void* p) {
    uint32_t a;
    asm("{ .reg .u64 t; cvta.to.shared.u64 t, %1; cvt.u32.u64 %0, t; }" : "=r"(a) : "l"(p));
    return a;
}
__device__ __forceinline__ void cp16(uint32_t s, const void* g) {
    asm volatile("cp.async.cg.shared.global [%0], [%1], 16;" :: "r"(s), "l"(g));
}
__device__ __forceinline__ void ldsm4(uint32_t& r0, uint32_t& r1, uint32_t& r2, uint32_t& r3,
                                      uint32_t addr) {
    asm volatile("ldmatrix.sync.aligned.m8n8.x4.shared.b16 {%0,%1,%2,%3}, [%4];"
                 : "=r"(r0), "=r"(r1), "=r"(r2), "=r"(r3) : "r"(addr));
}
__device__ __forceinline__ void mma_f16(float* c, const uint32_t* a, uint32_t b0, uint32_t b1) {
    asm volatile(
        "mma.sync.aligned.m16n8k16.row.col.f32.f16.f16.f32 "
        "{%0,%1,%2,%3}, {%4,%5,%6,%7}, {%8,%9}, {%0,%1,%2,%3};"
        : "+f"(c[0]), "+f"(c[1]), "+f"(c[2]), "+f"(c[3])
        : "r"(a[0]), "r"(a[1]), "r"(a[2]), "r"(a[3]), "r"(b0), "r"(b1));
}

__global__ void zero_counts_kernel() {
    if (threadIdx.x < E) g_cnt[threadIdx.x] = 0;
}

// ---------------- convert weights to fp16 ----------------
__global__ void convert_w_kernel(const float* __restrict__ w1,
                                 const float* __restrict__ w2)
{
    size_t n = (size_t)E * D * D / 4;
    size_t i = (size_t)blockIdx.x * blockDim.x + threadIdx.x;
    size_t stride = (size_t)gridDim.x * blockDim.x;
    for (; i < n; i += stride) {
        float4 v1 = ((const float4*)w1)[i];
        __half2* o1 = (__half2*)g_W1h + i * 2;
        o1[0] = __floats2half2_rn(v1.x, v1.y);
        o1[1] = __floats2half2_rn(v1.z, v1.w);
        float4 v2 = ((const float4*)w2)[i];
        __half2* o2 = (__half2*)g_W2h + i * 2;
        o2[0] = __floats2half2_rn(v2.x, v2.y);
        o2[1] = __floats2half2_rn(v2.z, v2.w);
    }
}

// ---------------- gating (emits fp16 x) ----------------
__global__ void gate_kernel(const float* __restrict__ x,
                            const float* __restrict__ gW,
                            const float* __restrict__ gb,
                            float* __restrict__ gate_prob_out,
                            int N)
{
    int token = blockIdx.x;
    if (token >= N) return;

    __shared__ float sx[D];
    __shared__ float slog[E];

    const float* xr = x + (size_t)token * D;
    __half* xout = g_xh + (size_t)token * D;
    for (int i = threadIdx.x; i < D; i += blockDim.x) {
        float v = xr[i];
        sx[i] = v;
        xout[i] = __float2half_rn(v);
    }
    __syncthreads();

    int w = threadIdx.x >> 5, lane = threadIdx.x & 31;
    float s = 0.f;
    const float* wr = gW + w * D;
    for (int k = lane; k < D; k += 32) s += sx[k] * wr[k];
    #pragma unroll
    for (int o = 16; o; o >>= 1) s += __shfl_xor_sync(0xffffffffu, s, o);
    if (lane == 0) slog[w] = s + gb[w];
    __syncthreads();

    if (threadIdx.x == 0) {
        float p[E];
        float mx = -1e30f;
        #pragma unroll
        for (int e = 0; e < E; e++) mx = fmaxf(mx, slog[e]);
        float sum = 0.f;
        #pragma unroll
        for (int e = 0; e < E; e++) { p[e] = expf(slog[e] - mx); sum += p[e]; }
        float inv = 1.f / sum;

        int i0 = 0; float p0 = -1.f;
        #pragma unroll
        for (int e = 0; e < E; e++) {
            p[e] *= inv;
            gate_prob_out[(size_t)token * E + e] = p[e];
            if (p[e] > p0) { p0 = p[e]; i0 = e; }
        }
        int i1 = -1; float p1 = -1.f;
        #pragma unroll
        for (int e = 0; e < E; e++)
            if (e != i0 && p[e] > p1) { p1 = p[e]; i1 = e; }

        float e1 = expf(p1 - p0);
        float w0 = 1.f / (1.f + e1);
        float w1 = e1 / (1.f + e1);

        int pos0 = atomicAdd(&g_cnt[i0], 1);
        int pos1 = atomicAdd(&g_cnt[i1], 1);
        g_tok[i0 * CAP + pos0] = token;
        g_tok[i1 * CAP + pos1] = token;
        g_slot[token * 2 + 0] = i0 * CAP + pos0;
        g_slot[token * 2 + 1] = i1 * CAP + pos1;
        g_wgt[token * 2 + 0] = w0;
        g_wgt[token * 2 + 1] = w1;
    }
}

// ---------------- expert GEMM: 128x256 CTA tile, 16 warps of 32x64 ----------------
// mode 0: A = gathered g_xh rows, W = g_W1h -> g_Hh (relu + b1, half store)
// mode 1: A = g_Hh rows,          W = g_W2h -> g_O  (b2, float store)
__global__ __launch_bounds__(512, 1)
void expert_gemm_mma(const float* __restrict__ bias, int mode)
{
    int e  = blockIdx.z;
    int ne = g_cnt[e];
    int m0 = blockIdx.x * BM;
    if (m0 >= ne) return;
    int n0 = blockIdx.y * BN;

    extern __shared__ char sm[];
    uint32_t smb = smem_u32(sm);

    int tid = threadIdx.x;   // 0..511

    const __half* W = (mode == 0) ? g_W1h : g_W2h;

    // loaders: threads 0..127 -> A row tid; threads 128..383 -> B row tid-128; rest idle
    const __half* Rptr = nullptr;
    bool is_loader = (tid < BM + BN);
    if (tid < BM) {
        if (mode == 0) {
            int tok = (m0 + tid < ne) ? g_tok[e * CAP + m0 + tid] : 0;
            Rptr = g_xh + (size_t)tok * D;
        } else {
            Rptr = g_Hh + ((size_t)e * CAP + m0 + tid) * D;
        }
    } else if (is_loader) {
        Rptr = W + ((size_t)e * D + n0 + (tid - BM)) * D;
    }
    uint32_t r_sm = smb + (uint32_t)tid * (ROWPAD * 2);

    #define LOAD_STAGE(buf, k0) do {                                       \
        if (is_loader) {                                                    \
            uint32_t _off = (uint32_t)(buf) * STG_BYTES;                    \
            const __half* _rg = Rptr + (k0);                                \
            _Pragma("unroll")                                               \
            for (int _c = 0; _c < 8; _c++)                                  \
                cp16(r_sm + _off + _c * 16u, _rg + _c * 8);                 \
        }                                                                   \
        asm volatile("cp.async.commit_group;" ::: "memory");                \
    } while (0)

    LOAD_STAGE(0, 0);
    LOAD_STAGE(1, KCH);

    int wid = tid >> 5, lane = tid & 31;
    int g  = lane >> 2, tg = lane & 3;
    int wm = (wid >> 2) * 32;       // 4 warps in m (32 rows each)
    int wn = (wid & 3) * 64;        // 4 warps in n (64 cols each)

    // ldmatrix offsets (bytes within a stage)
    uint32_t a_off[2], b_off[4];
    #pragma unroll
    for (int mt = 0; mt < 2; mt++) {
        int row = wm + mt * 16 + (lane & 15);
        a_off[mt] = (uint32_t)(row * ROWPAD + (lane >> 4) * 8) * 2u;
    }
    #pragma unroll
    for (int nt2 = 0; nt2 < 4; nt2++) {
        int row = wn + nt2 * 16 + (lane & 7) + ((lane >> 4) & 1) * 8;
        b_off[nt2] = (uint32_t)((BM + row) * ROWPAD + ((lane >> 3) & 1) * 8) * 2u;
    }

    float acc[2][8][4];
    #pragma unroll
    for (int mt = 0; mt < 2; mt++)
        #pragma unroll
        for (int nt = 0; nt < 8; nt++)
            #pragma unroll
            for (int i = 0; i < 4; i++) acc[mt][nt][i] = 0.f;

    #pragma unroll 1
    for (int s = 0; s < NSTAGE; s++) {
        if (s < NSTAGE - 1) asm volatile("cp.async.wait_group 1;" ::: "memory");
        else                asm volatile("cp.async.wait_group 0;" ::: "memory");
        __syncthreads();

        if (s + 2 < NSTAGE) LOAD_STAGE((s + 2) % 3, (s + 2) * KCH);

        uint32_t stg = smb + (uint32_t)(s % 3) * STG_BYTES;

        #pragma unroll
        for (int kk = 0; kk < KCH / 16; kk++) {
            uint32_t koff = (uint32_t)kk * 32u;   // 16 halfs
            uint32_t a[2][4], b[4][4];
            #pragma unroll
            for (int mt = 0; mt < 2; mt++)
                ldsm4(a[mt][0], a[mt][1], a[mt][2], a[mt][3], stg + a_off[mt] + koff);
            #pragma unroll
            for (int nt2 = 0; nt2 < 4; nt2++)
                ldsm4(b[nt2][0], b[nt2][1], b[nt2][2], b[nt2][3], stg + b_off[nt2] + koff);
            #pragma unroll
            for (int mt = 0; mt < 2; mt++)
                #pragma unroll
                for (int nt = 0; nt < 8; nt++)
                    mma_f16(acc[mt][nt], a[mt], b[nt >> 1][(nt & 1) * 2], b[nt >> 1][(nt & 1) * 2 + 1]);
        }
    }

    // ---------------- epilogue ----------------
    const float* brw = bias + (size_t)e * D + n0;

    #pragma unroll
    for (int mt = 0; mt < 2; mt++) {
        #pragma unroll
        for (int rr = 0; rr < 2; rr++) {
            int m = m0 + wm + mt * 16 + rr * 8 + g;
            if (m >= ne) continue;
            size_t rowbase = ((size_t)e * CAP + m) * D + n0;
            #pragma unroll
            for (int nt = 0; nt < 8; nt++) {
                int col = wn + nt * 8 + tg * 2;
                float v0 = acc[mt][nt][rr * 2 + 0] + brw[col];
                float v1 = acc[mt][nt][rr * 2 + 1] + brw[col + 1];
                if (mode == 0) {
                    v0 = fmaxf(v0, 0.f);
                    v1 = fmaxf(v1, 0.f);
                    *(__half2*)(g_Hh + rowbase + col) = __floats2half2_rn(v0, v1);
                } else {
                    *(float2*)(g_O + rowbase + col) = make_float2(v0, v1);
                }
            }
        }
    }
}

// ---------------- combine ----------------
__global__ void combine_kernel(float* __restrict__ y, int N)
{
    int token = blockIdx.x;
    if (token >= N) return;
    int   s0 = g_slot[token * 2 + 0];
    int   s1 = g_slot[token * 2 + 1];
    float w0 = g_wgt[token * 2 + 0];
    float w1 = g_wgt[token * 2 + 1];
    const float* o0 = g_O + (size_t)s0 * D;
    const float* o1 = g_O + (size_t)s1 * D;
    float* yr = y + (size_t)token * D;
    for (int i = threadIdx.x; i < D; i += blockDim.x)
        yr[i] = w0 * o0[i] + w1 * o1[i];
}

extern "C" void kernel_launch(void* const* d_in, const int* in_sizes, int n_in,
                              void* d_out, int out_size)
{
    const float* x  = (const float*)d_in[0];
    const float* gW = (const float*)d_in[1];
    const float* gb = (const float*)d_in[2];
    const float* w1 = (const float*)d_in[3];
    const float* b1 = (const float*)d_in[4];
    const float* w2 = (const float*)d_in[5];
    const float* b2 = (const float*)d_in[6];

    int N = in_sizes[0] / D;   // 4096

    float* y         = (float*)d_out;
    float* gate_prob = (float*)d_out + (size_t)N * D;

    static int smem_set = 0;
    if (!smem_set) {
        cudaFuncSetAttribute(expert_gemm_mma,
                             cudaFuncAttributeMaxDynamicSharedMemorySize, SMEM_BYTES);
        smem_set = 1;
    }

    zero_counts_kernel<<<1, 32>>>();
    convert_w_kernel<<<1184, 256>>>(w1, w2);
    gate_kernel<<<N, 256>>>(x, gW, gb, gate_prob, N);

    dim3 grid(NMAX / BM, D / BN, E);   // 32 x 4 x 8, inactive tiles exit early
    expert_gemm_mma<<<grid, 512, SMEM_BYTES>>>(b1, 0);
    expert_gemm_mma<<<grid, 512, SMEM_BYTES>>>(b2, 1);

    combine_kernel<<<N, 256>>>(y, N);
}

// round 11
// speedup vs baseline: 1.9719x; 1.0013x over previous
#include <cuda_runtime.h>
#include <cuda_fp16.h>
#include <math.h>
#include <stdint.h>

#define E 8
#define D 1024
#define NMAX 4096
#define CAP 4096

#define BM 128
#define BN 256
#define KCH 128                // halfs of K per stage
#define NSTAGE (D / KCH)       // 8
#define ROWPAD 136             // halfs per smem row (272B = 17*16B; ldmatrix conflict-free)
#define STG_BYTES ((BM + BN) * ROWPAD * 2)   // 104448
#define SMEM_BYTES (2 * STG_BYTES)           // 208896

// ---------------- scratch (device globals; no runtime allocation) ----------------
__device__ __half g_Hh[(size_t)E * CAP * D];
__device__ float  g_O[(size_t)E * CAP * D];
__device__ __half g_xh[(size_t)NMAX * D];
__device__ __half g_W1h[(size_t)E * D * D];
__device__ __half g_W2h[(size_t)E * D * D];
__device__ int    g_cnt[E];
__device__ int    g_tok[E * CAP];
__device__ int    g_slot[NMAX * 2];
__device__ float  g_wgt[NMAX * 2];

// ---------------- helpers ----------------
__device__ __forceinline__ uint32_t smem_u32(const void* p) {
    uint32_t a;
    asm("{ .reg .u64 t; cvta.to.shared.u64 t, %1; cvt.u32.u64 %0, t; }" : "=r"(a) : "l"(p));
    return a;
}
__device__ __forceinline__ void cp16(uint32_t s, const void* g) {
    asm volatile("cp.async.cg.shared.global [%0], [%1], 16;" :: "r"(s), "l"(g));
}
__device__ __forceinline__ void ldsm4(uint32_t& r0, uint32_t& r1, uint32_t& r2, uint32_t& r3,
                                      uint32_t addr) {
    asm volatile("ldmatrix.sync.aligned.m8n8.x4.shared.b16 {%0,%1,%2,%3}, [%4];"
                 : "=r"(r0), "=r"(r1), "=r"(r2), "=r"(r3) : "r"(addr));
}
__device__ __forceinline__ void mma_f16(float* c, const uint32_t* a, uint32_t b0, uint32_t b1) {
    asm volatile(
        "mma.sync.aligned.m16n8k16.row.col.f32.f16.f16.f32 "
        "{%0,%1,%2,%3}, {%4,%5,%6,%7}, {%8,%9}, {%0,%1,%2,%3};"
        : "+f"(c[0]), "+f"(c[1]), "+f"(c[2]), "+f"(c[3])
        : "r"(a[0]), "r"(a[1]), "r"(a[2]), "r"(a[3]), "r"(b0), "r"(b1));
}

__global__ void zero_counts_kernel() {
    if (threadIdx.x < E) g_cnt[threadIdx.x] = 0;
}

// ---------------- convert weights to fp16 ----------------
__global__ void convert_w_kernel(const float* __restrict__ w1,
                                 const float* __restrict__ w2)
{
    size_t n = (size_t)E * D * D / 4;
    size_t i = (size_t)blockIdx.x * blockDim.x + threadIdx.x;
    size_t stride = (size_t)gridDim.x * blockDim.x;
    for (; i < n; i += stride) {
        float4 v1 = ((const float4*)w1)[i];
        __half2* o1 = (__half2*)g_W1h + i * 2;
        o1[0] = __floats2half2_rn(v1.x, v1.y);
        o1[1] = __floats2half2_rn(v1.z, v1.w);
        float4 v2 = ((const float4*)w2)[i];
        __half2* o2 = (__half2*)g_W2h + i * 2;
        o2[0] = __floats2half2_rn(v2.x, v2.y);
        o2[1] = __floats2half2_rn(v2.z, v2.w);
    }
}

// ---------------- gating (emits fp16 x) ----------------
__global__ void gate_kernel(const float* __restrict__ x,
                            const float* __restrict__ gW,
                            const float* __restrict__ gb,
                            float* __restrict__ gate_prob_out,
                            int N)
{
    int token = blockIdx.x;
    if (token >= N) return;

    __shared__ float sx[D];
    __shared__ float slog[E];

    const float* xr = x + (size_t)token * D;
    __half* xout = g_xh + (size_t)token * D;
    for (int i = threadIdx.x; i < D; i += blockDim.x) {
        float v = xr[i];
        sx[i] = v;
        xout[i] = __float2half_rn(v);
    }
    __syncthreads();

    int w = threadIdx.x >> 5, lane = threadIdx.x & 31;
    float s = 0.f;
    const float* wr = gW + w * D;
    for (int k = lane; k < D; k += 32) s += sx[k] * wr[k];
    #pragma unroll
    for (int o = 16; o; o >>= 1) s += __shfl_xor_sync(0xffffffffu, s, o);
    if (lane == 0) slog[w] = s + gb[w];
    __syncthreads();

    if (threadIdx.x == 0) {
        float p[E];
        float mx = -1e30f;
        #pragma unroll
        for (int e = 0; e < E; e++) mx = fmaxf(mx, slog[e]);
        float sum = 0.f;
        #pragma unroll
        for (int e = 0; e < E; e++) { p[e] = expf(slog[e] - mx); sum += p[e]; }
        float inv = 1.f / sum;

        int i0 = 0; float p0 = -1.f;
        #pragma unroll
        for (int e = 0; e < E; e++) {
            p[e] *= inv;
            gate_prob_out[(size_t)token * E + e] = p[e];
            if (p[e] > p0) { p0 = p[e]; i0 = e; }
        }
        int i1 = -1; float p1 = -1.f;
        #pragma unroll
        for (int e = 0; e < E; e++)
            if (e != i0 && p[e] > p1) { p1 = p[e]; i1 = e; }

        float e1 = expf(p1 - p0);
        float w0 = 1.f / (1.f + e1);
        float w1 = e1 / (1.f + e1);

        int pos0 = atomicAdd(&g_cnt[i0], 1);
        int pos1 = atomicAdd(&g_cnt[i1], 1);
        g_tok[i0 * CAP + pos0] = token;
        g_tok[i1 * CAP + pos1] = token;
        g_slot[token * 2 + 0] = i0 * CAP + pos0;
        g_slot[token * 2 + 1] = i1 * CAP + pos1;
        g_wgt[token * 2 + 0] = w0;
        g_wgt[token * 2 + 1] = w1;
    }
}

// ---------------- expert GEMM: 128x256 CTA tile, 16 warps of 32x64, K=128 stages ----------------
// mode 0: A = gathered g_xh rows, W = g_W1h -> g_Hh (relu + b1, half store)
// mode 1: A = g_Hh rows,          W = g_W2h -> g_O  (b2, float store)
__global__ __launch_bounds__(512, 1)
void expert_gemm_mma(const float* __restrict__ bias, int mode)
{
    int e  = blockIdx.z;
    int ne = g_cnt[e];
    int m0 = blockIdx.x * BM;
    if (m0 >= ne) return;
    int n0 = blockIdx.y * BN;

    extern __shared__ char sm[];
    uint32_t smb = smem_u32(sm);

    int tid = threadIdx.x;   // 0..511

    const __half* W = (mode == 0) ? g_W1h : g_W2h;

    // loaders: threads 0..127 -> A row tid; threads 128..383 -> B row tid-128; rest idle
    const __half* Rptr = nullptr;
    bool is_loader = (tid < BM + BN);
    if (tid < BM) {
        if (mode == 0) {
            int tok = (m0 + tid < ne) ? g_tok[e * CAP + m0 + tid] : 0;
            Rptr = g_xh + (size_t)tok * D;
        } else {
            Rptr = g_Hh + ((size_t)e * CAP + m0 + tid) * D;
        }
    } else if (is_loader) {
        Rptr = W + ((size_t)e * D + n0 + (tid - BM)) * D;
    }
    uint32_t r_sm = smb + (uint32_t)tid * (ROWPAD * 2);

    #define LOAD_STAGE(buf, k0) do {                                       \
        if (is_loader) {                                                    \
            uint32_t _off = (uint32_t)(buf) * STG_BYTES;                    \
            const __half* _rg = Rptr + (k0);                                \
            _Pragma("unroll")                                               \
            for (int _c = 0; _c < 16; _c++)                                 \
                cp16(r_sm + _off + _c * 16u, _rg + _c * 8);                 \
        }                                                                   \
        asm volatile("cp.async.commit_group;" ::: "memory");                \
    } while (0)

    LOAD_STAGE(0, 0);

    int wid = tid >> 5, lane = tid & 31;
    int g  = lane >> 2, tg = lane & 3;
    int wm = (wid >> 2) * 32;       // 4 warps in m (32 rows each)
    int wn = (wid & 3) * 64;        // 4 warps in n (64 cols each)

    // ldmatrix offsets (bytes within a stage)
    uint32_t a_off[2], b_off[4];
    #pragma unroll
    for (int mt = 0; mt < 2; mt++) {
        int row = wm + mt * 16 + (lane & 15);
        a_off[mt] = (uint32_t)(row * ROWPAD + (lane >> 4) * 8) * 2u;
    }
    #pragma unroll
    for (int nt2 = 0; nt2 < 4; nt2++) {
        int row = wn + nt2 * 16 + (lane & 7) + ((lane >> 4) & 1) * 8;
        b_off[nt2] = (uint32_t)((BM + row) * ROWPAD + ((lane >> 3) & 1) * 8) * 2u;
    }

    float acc[2][8][4];
    #pragma unroll
    for (int mt = 0; mt < 2; mt++)
        #pragma unroll
        for (int nt = 0; nt < 8; nt++)
            #pragma unroll
            for (int i = 0; i < 4; i++) acc[mt][nt][i] = 0.f;

    #pragma unroll 1
    for (int s = 0; s < NSTAGE; s++) {
        asm volatile("cp.async.wait_group 0;" ::: "memory");  // stage s resident
        __syncthreads();   // data visible; all warps done with buffer (s+1)&1

        if (s + 1 < NSTAGE) LOAD_STAGE((s + 1) & 1, (s + 1) * KCH);

        uint32_t stg = smb + (uint32_t)(s & 1) * STG_BYTES;

        #pragma unroll
        for (int kk = 0; kk < KCH / 16; kk++) {
            uint32_t koff = (uint32_t)kk * 32u;   // 16 halfs
            uint32_t a[2][4], b[4][4];
            #pragma unroll
            for (int mt = 0; mt < 2; mt++)
                ldsm4(a[mt][0], a[mt][1], a[mt][2], a[mt][3], stg + a_off[mt] + koff);
            #pragma unroll
            for (int nt2 = 0; nt2 < 4; nt2++)
                ldsm4(b[nt2][0], b[nt2][1], b[nt2][2], b[nt2][3], stg + b_off[nt2] + koff);
            #pragma unroll
            for (int mt = 0; mt < 2; mt++)
                #pragma unroll
                for (int nt = 0; nt < 8; nt++)
                    mma_f16(acc[mt][nt], a[mt], b[nt >> 1][(nt & 1) * 2], b[nt >> 1][(nt & 1) * 2 + 1]);
        }
    }

    // ---------------- epilogue ----------------
    const float* brw = bias + (size_t)e * D + n0;

    #pragma unroll
    for (int mt = 0; mt < 2; mt++) {
        #pragma unroll
        for (int rr = 0; rr < 2; rr++) {
            int m = m0 + wm + mt * 16 + rr * 8 + g;
            if (m >= ne) continue;
            size_t rowbase = ((size_t)e * CAP + m) * D + n0;
            #pragma unroll
            for (int nt = 0; nt < 8; nt++) {
                int col = wn + nt * 8 + tg * 2;
                float v0 = acc[mt][nt][rr * 2 + 0] + brw[col];
                float v1 = acc[mt][nt][rr * 2 + 1] + brw[col + 1];
                if (mode == 0) {
                    v0 = fmaxf(v0, 0.f);
                    v1 = fmaxf(v1, 0.f);
                    *(__half2*)(g_Hh + rowbase + col) = __floats2half2_rn(v0, v1);
                } else {
                    *(float2*)(g_O + rowbase + col) = make_float2(v0, v1);
                }
            }
        }
    }
}

// ---------------- combine (float4) ----------------
__global__ void combine_kernel(float* __restrict__ y, int N)
{
    int token = blockIdx.x;
    if (token >= N) return;
    int   s0 = g_slot[token * 2 + 0];
    int   s1 = g_slot[token * 2 + 1];
    float w0 = g_wgt[token * 2 + 0];
    float w1 = g_wgt[token * 2 + 1];
    const float4* o0 = (const float4*)(g_O + (size_t)s0 * D);
    const float4* o1 = (const float4*)(g_O + (size_t)s1 * D);
    float4* yr = (float4*)(y + (size_t)token * D);
    for (int i = threadIdx.x; i < D / 4; i += blockDim.x) {
        float4 a = o0[i], b = o1[i];
        float4 r;
        r.x = w0 * a.x + w1 * b.x;
        r.y = w0 * a.y + w1 * b.y;
        r.z = w0 * a.z + w1 * b.z;
        r.w = w0 * a.w + w1 * b.w;
        yr[i] = r;
    }
}

extern "C" void kernel_launch(void* const* d_in, const int* in_sizes, int n_in,
                              void* d_out, int out_size)
{
    const float* x  = (const float*)d_in[0];
    const float* gW = (const float*)d_in[1];
    const float* gb = (const float*)d_in[2];
    const float* w1 = (const float*)d_in[3];
    const float* b1 = (const float*)d_in[4];
    const float* w2 = (const float*)d_in[5];
    const float* b2 = (const float*)d_in[6];

    int N = in_sizes[0] / D;   // 4096

    float* y         = (float*)d_out;
    float* gate_prob = (float*)d_out + (size_t)N * D;

    static int smem_set = 0;
    if (!smem_set) {
        cudaFuncSetAttribute(expert_gemm_mma,
                             cudaFuncAttributeMaxDynamicSharedMemorySize, SMEM_BYTES);
        smem_set = 1;
    }

    zero_counts_kernel<<<1, 32>>>();
    convert_w_kernel<<<1184, 256>>>(w1, w2);
    gate_kernel<<<N, 256>>>(x, gW, gb, gate_prob, N);

    dim3 grid(NMAX / BM, D / BN, E);   // 32 x 4 x 8, inactive tiles exit early
    expert_gemm_mma<<<grid, 512, SMEM_BYTES>>>(b1, 0);
    expert_gemm_mma<<<grid, 512, SMEM_BYTES>>>(b2, 1);

    combine_kernel<<<N, 256>>>(y, N);
}

// round 12
// speedup vs baseline: 2.8866x; 1.4639x over previous
#include <cuda_runtime.h>
#include <cuda_fp16.h>
#include <math.h>
#include <stdint.h>

#define E 8
#define D 1024
#define NMAX 4096
#define CAP 4096

#define BM 128
#define BN 256
#define KCH 128                // halfs of K per stage
#define NSTAGE (D / KCH)       // 8
#define ROWPAD 136             // halfs per smem row (272B = 17*16B; ldmatrix conflict-free)
#define ROWBYTES (KCH * 2)     // 256B payload per row per stage
#define STG_BYTES ((BM + BN) * ROWPAD * 2)     // 104448
#define TX_BYTES  ((BM + BN) * ROWBYTES)       // 98304 per stage
#define SMEM_BYTES (2 * STG_BYTES)             // 208896

// ---------------- scratch (device globals; no runtime allocation) ----------------
__device__ __half g_Hh[(size_t)E * CAP * D];
__device__ float  g_O[(size_t)E * CAP * D];
__device__ __half g_xh[(size_t)NMAX * D];
__device__ __half g_W1h[(size_t)E * D * D];
__device__ __half g_W2h[(size_t)E * D * D];
__device__ int    g_cnt[E];
__device__ int    g_tok[E * CAP];
__device__ int    g_slot[NMAX * 2];
__device__ float  g_wgt[NMAX * 2];

// ---------------- helpers ----------------
__device__ __forceinline__ uint32_t smem_u32(const void* p) {
    uint32_t a;
    asm("{ .reg .u64 t; cvta.to.shared.u64 t, %1; cvt.u32.u64 %0, t; }" : "=r"(a) : "l"(p));
    return a;
}
__device__ __forceinline__ void bulk_cp(uint32_t dst, const void* src, uint32_t bytes, uint32_t mbar) {
    asm volatile(
        "cp.async.bulk.shared::cta.global.mbarrier::complete_tx::bytes [%0], [%1], %2, [%3];"
        :: "r"(dst), "l"(src), "r"(bytes), "r"(mbar) : "memory");
}
__device__ __forceinline__ void mbar_init(uint32_t mbar, uint32_t count) {
    asm volatile("mbarrier.init.shared.b64 [%0], %1;" :: "r"(mbar), "r"(count) : "memory");
}
__device__ __forceinline__ void mbar_expect_tx(uint32_t mbar, uint32_t bytes) {
    asm volatile("mbarrier.arrive.expect_tx.shared.b64 _, [%0], %1;" :: "r"(mbar), "r"(bytes) : "memory");
}
__device__ __forceinline__ void mbar_wait(uint32_t mbar, uint32_t parity) {
    uint32_t done;
    asm volatile(
        "{\n\t.reg .pred p;\n\t"
        "mbarrier.try_wait.parity.shared.b64 p, [%1], %2;\n\t"
        "selp.b32 %0, 1, 0, p;\n\t}"
        : "=r"(done) : "r"(mbar), "r"(parity) : "memory");
    if (!done) {
        asm volatile(
            "{\n\t.reg .pred P1;\n\t"
            "WL_%=:\n\t"
            "mbarrier.try_wait.parity.shared.b64 P1, [%0], %1, 0x989680;\n\t"
            "@P1 bra.uni WD_%=;\n\t"
            "bra.uni WL_%=;\n\t"
            "WD_%=:\n\t}"
            :: "r"(mbar), "r"(parity) : "memory");
    }
}
__device__ __forceinline__ void ldsm4(uint32_t& r0, uint32_t& r1, uint32_t& r2, uint32_t& r3,
                                      uint32_t addr) {
    asm volatile("ldmatrix.sync.aligned.m8n8.x4.shared.b16 {%0,%1,%2,%3}, [%4];"
                 : "=r"(r0), "=r"(r1), "=r"(r2), "=r"(r3) : "r"(addr));
}
__device__ __forceinline__ void mma_f16(float* c, const uint32_t* a, uint32_t b0, uint32_t b1) {
    asm volatile(
        "mma.sync.aligned.m16n8k16.row.col.f32.f16.f16.f32 "
        "{%0,%1,%2,%3}, {%4,%5,%6,%7}, {%8,%9}, {%0,%1,%2,%3};"
        : "+f"(c[0]), "+f"(c[1]), "+f"(c[2]), "+f"(c[3])
        : "r"(a[0]), "r"(a[1]), "r"(a[2]), "r"(a[3]), "r"(b0), "r"(b1));
}

__global__ void zero_counts_kernel() {
    if (threadIdx.x < E) g_cnt[threadIdx.x] = 0;
}

// ---------------- convert weights to fp16 ----------------
__global__ void convert_w_kernel(const float* __restrict__ w1,
                                 const float* __restrict__ w2)
{
    size_t n = (size_t)E * D * D / 4;
    size_t i = (size_t)blockIdx.x * blockDim.x + threadIdx.x;
    size_t stride = (size_t)gridDim.x * blockDim.x;
    for (; i < n; i += stride) {
        float4 v1 = ((const float4*)w1)[i];
        __half2* o1 = (__half2*)g_W1h + i * 2;
        o1[0] = __floats2half2_rn(v1.x, v1.y);
        o1[1] = __floats2half2_rn(v1.z, v1.w);
        float4 v2 = ((const float4*)w2)[i];
        __half2* o2 = (__half2*)g_W2h + i * 2;
        o2[0] = __floats2half2_rn(v2.x, v2.y);
        o2[1] = __floats2half2_rn(v2.z, v2.w);
    }
}

// ---------------- gating (emits fp16 x) ----------------
__global__ void gate_kernel(const float* __restrict__ x,
                            const float* __restrict__ gW,
                            const float* __restrict__ gb,
                            float* __restrict__ gate_prob_out,
                            int N)
{
    int token = blockIdx.x;
    if (token >= N) return;

    __shared__ float sx[D];
    __shared__ float slog[E];

    const float* xr = x + (size_t)token * D;
    __half* xout = g_xh + (size_t)token * D;
    for (int i = threadIdx.x; i < D; i += blockDim.x) {
        float v = xr[i];
        sx[i] = v;
        xout[i] = __float2half_rn(v);
    }
    __syncthreads();

    int w = threadIdx.x >> 5, lane = threadIdx.x & 31;
    float s = 0.f;
    const float* wr = gW + w * D;
    for (int k = lane; k < D; k += 32) s += sx[k] * wr[k];
    #pragma unroll
    for (int o = 16; o; o >>= 1) s += __shfl_xor_sync(0xffffffffu, s, o);
    if (lane == 0) slog[w] = s + gb[w];
    __syncthreads();

    if (threadIdx.x == 0) {
        float p[E];
        float mx = -1e30f;
        #pragma unroll
        for (int e = 0; e < E; e++) mx = fmaxf(mx, slog[e]);
        float sum = 0.f;
        #pragma unroll
        for (int e = 0; e < E; e++) { p[e] = expf(slog[e] - mx); sum += p[e]; }
        float inv = 1.f / sum;

        int i0 = 0; float p0 = -1.f;
        #pragma unroll
        for (int e = 0; e < E; e++) {
            p[e] *= inv;
            gate_prob_out[(size_t)token * E + e] = p[e];
            if (p[e] > p0) { p0 = p[e]; i0 = e; }
        }
        int i1 = -1; float p1 = -1.f;
        #pragma unroll
        for (int e = 0; e < E; e++)
            if (e != i0 && p[e] > p1) { p1 = p[e]; i1 = e; }

        float e1 = expf(p1 - p0);
        float w0 = 1.f / (1.f + e1);
        float w1 = e1 / (1.f + e1);

        int pos0 = atomicAdd(&g_cnt[i0], 1);
        int pos1 = atomicAdd(&g_cnt[i1], 1);
        g_tok[i0 * CAP + pos0] = token;
        g_tok[i1 * CAP + pos1] = token;
        g_slot[token * 2 + 0] = i0 * CAP + pos0;
        g_slot[token * 2 + 1] = i1 * CAP + pos1;
        g_wgt[token * 2 + 0] = w0;
        g_wgt[token * 2 + 1] = w1;
    }
}

// ---------------- expert GEMM: bulk-async copy + fp16 mma ----------------
// mode 0: A = gathered g_xh rows, W = g_W1h -> g_Hh (relu + b1, half store)
// mode 1: A = g_Hh rows,          W = g_W2h -> g_O  (b2, float store)
__global__ __launch_bounds__(512, 1)
void expert_gemm_mma(const float* __restrict__ bias, int mode)
{
    int e  = blockIdx.z;
    int ne = g_cnt[e];
    int m0 = blockIdx.x * BM;
    if (m0 >= ne) return;
    int n0 = blockIdx.y * BN;

    extern __shared__ char sm[];
    __shared__ uint64_t mbar_store[2];
    uint32_t smb  = smem_u32(sm);
    uint32_t mbar = smem_u32(mbar_store);

    int tid = threadIdx.x;   // 0..511

    const __half* W = (mode == 0) ? g_W1h : g_W2h;

    // loaders: threads 0..127 -> A row tid; threads 128..383 -> B row tid-128
    const __half* Rptr = nullptr;
    bool is_loader = (tid < BM + BN);
    if (tid < BM) {
        if (mode == 0) {
            int tok = (m0 + tid < ne) ? g_tok[e * CAP + m0 + tid] : 0;
            Rptr = g_xh + (size_t)tok * D;
        } else {
            Rptr = g_Hh + ((size_t)e * CAP + m0 + tid) * D;
        }
    } else if (is_loader) {
        Rptr = W + ((size_t)e * D + n0 + (tid - BM)) * D;
    }
    uint32_t r_sm = smb + (uint32_t)tid * (ROWPAD * 2);

    if (tid == 0) { mbar_init(mbar, 1); mbar_init(mbar + 8, 1); }
    __syncthreads();

    // stage 0 issue
    if (tid == 0) mbar_expect_tx(mbar, TX_BYTES);
    __syncthreads();                       // expect_tx visible before complete_tx arrivals
    if (is_loader) bulk_cp(r_sm, Rptr, ROWBYTES, mbar);

    int wid = tid >> 5, lane = tid & 31;
    int g  = lane >> 2, tg = lane & 3;
    int wm = (wid >> 2) * 32;       // 4 warps in m (32 rows each)
    int wn = (wid & 3) * 64;        // 4 warps in n (64 cols each)

    // ldmatrix offsets (bytes within a stage)
    uint32_t a_off[2], b_off[4];
    #pragma unroll
    for (int mt = 0; mt < 2; mt++) {
        int row = wm + mt * 16 + (lane & 15);
        a_off[mt] = (uint32_t)(row * ROWPAD + (lane >> 4) * 8) * 2u;
    }
    #pragma unroll
    for (int nt2 = 0; nt2 < 4; nt2++) {
        int row = wn + nt2 * 16 + (lane & 7) + ((lane >> 4) & 1) * 8;
        b_off[nt2] = (uint32_t)((BM + row) * ROWPAD + ((lane >> 3) & 1) * 8) * 2u;
    }

    float acc[2][8][4];
    #pragma unroll
    for (int mt = 0; mt < 2; mt++)
        #pragma unroll
        for (int nt = 0; nt < 8; nt++)
            #pragma unroll
            for (int i = 0; i < 4; i++) acc[mt][nt][i] = 0.f;

    int ph[2] = {0, 0};

    #pragma unroll 1
    for (int s = 0; s < NSTAGE; s++) {
        int b = s & 1;
        mbar_wait(mbar + b * 8, ph[b]);    // stage s data resident
        ph[b] ^= 1;
        __syncthreads();                   // all threads past stage s-1 compute (WAR-safe)

        if (s + 1 < NSTAGE) {
            int nb = (s + 1) & 1;
            if (tid == 0) mbar_expect_tx(mbar + nb * 8, TX_BYTES);
            // no extra sync needed: tx-count may go transiently negative; HW handles order
            if (is_loader)
                bulk_cp(r_sm + (uint32_t)nb * STG_BYTES, Rptr + (s + 1) * KCH, ROWBYTES, mbar + nb * 8);
        }

        uint32_t stg = smb + (uint32_t)b * STG_BYTES;

        #pragma unroll
        for (int kk = 0; kk < KCH / 16; kk++) {
            uint32_t koff = (uint32_t)kk * 32u;   // 16 halfs
            uint32_t a[2][4], bfr[4][4];
            #pragma unroll
            for (int mt = 0; mt < 2; mt++)
                ldsm4(a[mt][0], a[mt][1], a[mt][2], a[mt][3], stg + a_off[mt] + koff);
            #pragma unroll
            for (int nt2 = 0; nt2 < 4; nt2++)
                ldsm4(bfr[nt2][0], bfr[nt2][1], bfr[nt2][2], bfr[nt2][3], stg + b_off[nt2] + koff);
            #pragma unroll
            for (int mt = 0; mt < 2; mt++)
                #pragma unroll
                for (int nt = 0; nt < 8; nt++)
                    mma_f16(acc[mt][nt], a[mt], bfr[nt >> 1][(nt & 1) * 2], bfr[nt >> 1][(nt & 1) * 2 + 1]);
        }
    }

    // ---------------- epilogue ----------------
    const float* brw = bias + (size_t)e * D + n0;

    #pragma unroll
    for (int mt = 0; mt < 2; mt++) {
        #pragma unroll
        for (int rr = 0; rr < 2; rr++) {
            int m = m0 + wm + mt * 16 + rr * 8 + g;
            if (m >= ne) continue;
            size_t rowbase = ((size_t)e * CAP + m) * D + n0;
            #pragma unroll
            for (int nt = 0; nt < 8; nt++) {
                int col = wn + nt * 8 + tg * 2;
                float v0 = acc[mt][nt][rr * 2 + 0] + brw[col];
                float v1 = acc[mt][nt][rr * 2 + 1] + brw[col + 1];
                if (mode == 0) {
                    v0 = fmaxf(v0, 0.f);
                    v1 = fmaxf(v1, 0.f);
                    *(__half2*)(g_Hh + rowbase + col) = __floats2half2_rn(v0, v1);
                } else {
                    *(float2*)(g_O + rowbase + col) = make_float2(v0, v1);
                }
            }
        }
    }
}

// ---------------- combine (float4) ----------------
__global__ void combine_kernel(float* __restrict__ y, int N)
{
    int token = blockIdx.x;
    if (token >= N) return;
    int   s0 = g_slot[token * 2 + 0];
    int   s1 = g_slot[token * 2 + 1];
    float w0 = g_wgt[token * 2 + 0];
    float w1 = g_wgt[token * 2 + 1];
    const float4* o0 = (const float4*)(g_O + (size_t)s0 * D);
    const float4* o1 = (const float4*)(g_O + (size_t)s1 * D);
    float4* yr = (float4*)(y + (size_t)token * D);
    for (int i = threadIdx.x; i < D / 4; i += blockDim.x) {
        float4 a = o0[i], b = o1[i];
        float4 r;
        r.x = w0 * a.x + w1 * b.x;
        r.y = w0 * a.y + w1 * b.y;
        r.z = w0 * a.z + w1 * b.z;
        r.w = w0 * a.w + w1 * b.w;
        yr[i] = r;
    }
}

extern "C" void kernel_launch(void* const* d_in, const int* in_sizes, int n_in,
                              void* d_out, int out_size)
{
    const float* x  = (const float*)d_in[0];
    const float* gW = (const float*)d_in[1];
    const float* gb = (const float*)d_in[2];
    const float* w1 = (const float*)d_in[3];
    const float* b1 = (const float*)d_in[4];
    const float* w2 = (const float*)d_in[5];
    const float* b2 = (const float*)d_in[6];

    int N = in_sizes[0] / D;   // 4096

    float* y         = (float*)d_out;
    float* gate_prob = (float*)d_out + (size_t)N * D;

    static int smem_set = 0;
    if (!smem_set) {
        cudaFuncSetAttribute(expert_gemm_mma,
                             cudaFuncAttributeMaxDynamicSharedMemorySize, SMEM_BYTES);
        smem_set = 1;
    }

    zero_counts_kernel<<<1, 32>>>();
    convert_w_kernel<<<1184, 256>>>(w1, w2);
    gate_kernel<<<N, 256>>>(x, gW, gb, gate_prob, N);

    dim3 grid(NMAX / BM, D / BN, E);   // 32 x 4 x 8, inactive tiles exit early
    expert_gemm_mma<<<grid, 512, SMEM_BYTES>>>(b1, 0);
    expert_gemm_mma<<<grid, 512, SMEM_BYTES>>>(b2, 1);

    combine_kernel<<<N, 256>>>(y, N);
}

// round 13
// speedup vs baseline: 2.9635x; 1.0267x over previous
#include <cuda_runtime.h>
#include <cuda_fp16.h>
#include <math.h>
#include <stdint.h>

#define E 8
#define D 1024
#define NMAX 4096
#define CAP 4096

#define BM 128
#define BN 256
#define KCH 128                // halfs of K per stage
#define NSTAGE (D / KCH)       // 8
#define ROWPAD 136             // halfs per smem row (272B)
#define ROWBYTES (KCH * 2)     // 256B payload per row per stage
#define STG_BYTES ((BM + BN) * ROWPAD * 2)     // 104448
#define TX_BYTES  ((BM + BN) * ROWBYTES)       // 98304 per stage
#define SMEM_BYTES (2 * STG_BYTES)             // 208896

#define MT_TILES (NMAX / BM)       // 32
#define NT_TILES (D / BN)          // 4
#define TILES_PER_PASS (MT_TILES * E * NT_TILES)   // 1024
#define TOTAL_TILES (2 * TILES_PER_PASS)           // 2048

// ---------------- scratch (device globals; no runtime allocation) ----------------
__device__ __half g_Hh[(size_t)E * CAP * D];
__device__ float  g_O[(size_t)E * CAP * D];
__device__ __half g_xh[(size_t)NMAX * D];
__device__ __half g_W1h[(size_t)E * D * D];
__device__ __half g_W2h[(size_t)E * D * D];
__device__ int    g_cnt[E];
__device__ int    g_tok[E * CAP];
__device__ int    g_slot[NMAX * 2];
__device__ float  g_wgt[NMAX * 2];
__device__ int    g_tile_ctr;
__device__ int    g_ready[E * MT_TILES];

// ---------------- helpers ----------------
__device__ __forceinline__ uint32_t smem_u32(const void* p) {
    uint32_t a;
    asm("{ .reg .u64 t; cvta.to.shared.u64 t, %1; cvt.u32.u64 %0, t; }" : "=r"(a) : "l"(p));
    return a;
}
__device__ __forceinline__ void bulk_cp(uint32_t dst, const void* src, uint32_t bytes, uint32_t mbar) {
    asm volatile(
        "cp.async.bulk.shared::cta.global.mbarrier::complete_tx::bytes [%0], [%1], %2, [%3];"
        :: "r"(dst), "l"(src), "r"(bytes), "r"(mbar) : "memory");
}
__device__ __forceinline__ void mbar_init(uint32_t mbar, uint32_t count) {
    asm volatile("mbarrier.init.shared.b64 [%0], %1;" :: "r"(mbar), "r"(count) : "memory");
}
__device__ __forceinline__ void mbar_expect_tx(uint32_t mbar, uint32_t bytes) {
    asm volatile("mbarrier.arrive.expect_tx.shared.b64 _, [%0], %1;" :: "r"(mbar), "r"(bytes) : "memory");
}
__device__ __forceinline__ void mbar_wait(uint32_t mbar, uint32_t parity) {
    uint32_t done;
    asm volatile(
        "{\n\t.reg .pred p;\n\t"
        "mbarrier.try_wait.parity.shared.b64 p, [%1], %2;\n\t"
        "selp.b32 %0, 1, 0, p;\n\t}"
        : "=r"(done) : "r"(mbar), "r"(parity) : "memory");
    if (!done) {
        asm volatile(
            "{\n\t.reg .pred P1;\n\t"
            "WL_%=:\n\t"
            "mbarrier.try_wait.parity.shared.b64 P1, [%0], %1, 0x989680;\n\t"
            "@P1 bra.uni WD_%=;\n\t"
            "bra.uni WL_%=;\n\t"
            "WD_%=:\n\t}"
            :: "r"(mbar), "r"(parity) : "memory");
    }
}
__device__ __forceinline__ void ldsm4(uint32_t& r0, uint32_t& r1, uint32_t& r2, uint32_t& r3,
                                      uint32_t addr) {
    asm volatile("ldmatrix.sync.aligned.m8n8.x4.shared.b16 {%0,%1,%2,%3}, [%4];"
                 : "=r"(r0), "=r"(r1), "=r"(r2), "=r"(r3) : "r"(addr));
}
__device__ __forceinline__ void mma_f16(float* c, const uint32_t* a, uint32_t b0, uint32_t b1) {
    asm volatile(
        "mma.sync.aligned.m16n8k16.row.col.f32.f16.f16.f32 "
        "{%0,%1,%2,%3}, {%4,%5,%6,%7}, {%8,%9}, {%0,%1,%2,%3};"
        : "+f"(c[0]), "+f"(c[1]), "+f"(c[2]), "+f"(c[3])
        : "r"(a[0]), "r"(a[1]), "r"(a[2]), "r"(a[3]), "r"(b0), "r"(b1));
}

__global__ void zero_counts_kernel() {
    if (threadIdx.x < E) g_cnt[threadIdx.x] = 0;
    if (threadIdx.x == 0) g_tile_ctr = 0;
    for (int i = threadIdx.x; i < E * MT_TILES; i += 32) g_ready[i] = 0;
}

// ---------------- convert weights to fp16 ----------------
__global__ void convert_w_kernel(const float* __restrict__ w1,
                                 const float* __restrict__ w2)
{
    size_t n = (size_t)E * D * D / 4;
    size_t i = (size_t)blockIdx.x * blockDim.x + threadIdx.x;
    size_t stride = (size_t)gridDim.x * blockDim.x;
    for (; i < n; i += stride) {
        float4 v1 = ((const float4*)w1)[i];
        __half2* o1 = (__half2*)g_W1h + i * 2;
        o1[0] = __floats2half2_rn(v1.x, v1.y);
        o1[1] = __floats2half2_rn(v1.z, v1.w);
        float4 v2 = ((const float4*)w2)[i];
        __half2* o2 = (__half2*)g_W2h + i * 2;
        o2[0] = __floats2half2_rn(v2.x, v2.y);
        o2[1] = __floats2half2_rn(v2.z, v2.w);
    }
}

// ---------------- gating (emits fp16 x) ----------------
__global__ void gate_kernel(const float* __restrict__ x,
                            const float* __restrict__ gW,
                            const float* __restrict__ gb,
                            float* __restrict__ gate_prob_out,
                            int N)
{
    int token = blockIdx.x;
    if (token >= N) return;

    __shared__ float sx[D];
    __shared__ float slog[E];

    const float* xr = x + (size_t)token * D;
    __half* xout = g_xh + (size_t)token * D;
    for (int i = threadIdx.x; i < D; i += blockDim.x) {
        float v = xr[i];
        sx[i] = v;
        xout[i] = __float2half_rn(v);
    }
    __syncthreads();

    int w = threadIdx.x >> 5, lane = threadIdx.x & 31;
    float s = 0.f;
    const float* wr = gW + w * D;
    for (int k = lane; k < D; k += 32) s += sx[k] * wr[k];
    #pragma unroll
    for (int o = 16; o; o >>= 1) s += __shfl_xor_sync(0xffffffffu, s, o);
    if (lane == 0) slog[w] = s + gb[w];
    __syncthreads();

    if (threadIdx.x == 0) {
        float p[E];
        float mx = -1e30f;
        #pragma unroll
        for (int e = 0; e < E; e++) mx = fmaxf(mx, slog[e]);
        float sum = 0.f;
        #pragma unroll
        for (int e = 0; e < E; e++) { p[e] = expf(slog[e] - mx); sum += p[e]; }
        float inv = 1.f / sum;

        int i0 = 0; float p0 = -1.f;
        #pragma unroll
        for (int e = 0; e < E; e++) {
            p[e] *= inv;
            gate_prob_out[(size_t)token * E + e] = p[e];
            if (p[e] > p0) { p0 = p[e]; i0 = e; }
        }
        int i1 = -1; float p1 = -1.f;
        #pragma unroll
        for (int e = 0; e < E; e++)
            if (e != i0 && p[e] > p1) { p1 = p[e]; i1 = e; }

        float e1 = expf(p1 - p0);
        float w0 = 1.f / (1.f + e1);
        float w1 = e1 / (1.f + e1);

        int pos0 = atomicAdd(&g_cnt[i0], 1);
        int pos1 = atomicAdd(&g_cnt[i1], 1);
        g_tok[i0 * CAP + pos0] = token;
        g_tok[i1 * CAP + pos1] = token;
        g_slot[token * 2 + 0] = i0 * CAP + pos0;
        g_slot[token * 2 + 1] = i1 * CAP + pos1;
        g_wgt[token * 2 + 0] = w0;
        g_wgt[token * 2 + 1] = w1;
    }
}

// ---------------- persistent fused two-pass expert GEMM ----------------
// Tile queue: ids [0, 1024) = pass 1, [1024, 2048) = pass 2.
// id-within-pass = mt*32 + e*4 + nt  (m-tile major: low ids are active tiles).
// Pass 1 publishes g_ready[e*32+mt] (4 n-tiles); pass 2 spins on it.
__global__ __launch_bounds__(512, 1)
void expert_gemm_persistent(const float* __restrict__ b1,
                            const float* __restrict__ b2)
{
    extern __shared__ char sm[];
    __shared__ uint64_t mbar_store[2];
    __shared__ int s_tile;
    uint32_t smb  = smem_u32(sm);
    uint32_t mbar = smem_u32(mbar_store);

    int tid = threadIdx.x;   // 0..511
    int wid = tid >> 5, lane = tid & 31;
    int g  = lane >> 2, tg = lane & 3;
    int wm = (wid >> 2) * 32;       // 4 warps in m (32 rows each)
    int wn = (wid & 3) * 64;        // 4 warps in n (64 cols each)

    if (tid == 0) { mbar_init(mbar, 1); mbar_init(mbar + 8, 1); }
    __syncthreads();

    // ldmatrix offsets (bytes within a stage) — tile-independent
    uint32_t a_off[2], b_off[4];
    #pragma unroll
    for (int mt = 0; mt < 2; mt++) {
        int row = wm + mt * 16 + (lane & 15);
        a_off[mt] = (uint32_t)(row * ROWPAD + (lane >> 4) * 8) * 2u;
    }
    #pragma unroll
    for (int nt2 = 0; nt2 < 4; nt2++) {
        int row = wn + nt2 * 16 + (lane & 7) + ((lane >> 4) & 1) * 8;
        b_off[nt2] = (uint32_t)((BM + row) * ROWPAD + ((lane >> 3) & 1) * 8) * 2u;
    }

    bool is_loader = (tid < BM + BN);
    uint32_t r_sm = smb + (uint32_t)tid * (ROWPAD * 2);

    int ph[2] = {0, 0};   // mbarrier phases persist across tiles

    for (;;) {
        if (tid == 0) s_tile = atomicAdd(&g_tile_ctr, 1);
        __syncthreads();
        int t = s_tile;
        __syncthreads();
        if (t >= TOTAL_TILES) break;

        int mode = (t >= TILES_PER_PASS) ? 1 : 0;
        int idx  = mode ? (t - TILES_PER_PASS) : t;
        int mt_i = idx >> 5;
        int e    = (idx & 31) >> 2;
        int nt_i = idx & 3;
        int ne   = g_cnt[e];
        int m0   = mt_i * BM;
        int n0   = nt_i * BN;
        if (m0 >= ne) continue;            // inactive for both passes

        // pass-2: wait for this (e, m-tile) to be fully produced by pass-1
        if (mode == 1) {
            if (tid == 0) {
                const int* rp = &g_ready[e * MT_TILES + mt_i];
                int v;
                do {
                    asm volatile("ld.global.cg.s32 %0, [%1];" : "=r"(v) : "l"(rp) : "memory");
                } while (v < NT_TILES);
            }
            __syncthreads();
        }

        // per-tile loader pointer
        const __half* Rptr = nullptr;
        if (tid < BM) {
            if (mode == 0) {
                int tok = (m0 + tid < ne) ? g_tok[e * CAP + m0 + tid] : 0;
                Rptr = g_xh + (size_t)tok * D;
            } else {
                Rptr = g_Hh + ((size_t)e * CAP + m0 + tid) * D;
            }
        } else if (is_loader) {
            const __half* W = (mode == 0) ? g_W1h : g_W2h;
            Rptr = W + ((size_t)e * D + n0 + (tid - BM)) * D;
        }

        // stage 0 issue
        if (tid == 0) mbar_expect_tx(mbar, TX_BYTES);
        __syncthreads();
        if (is_loader) bulk_cp(r_sm, Rptr, ROWBYTES, mbar);

        float acc[2][8][4];
        #pragma unroll
        for (int mt = 0; mt < 2; mt++)
            #pragma unroll
            for (int nt = 0; nt < 8; nt++)
                #pragma unroll
                for (int i = 0; i < 4; i++) acc[mt][nt][i] = 0.f;

        #pragma unroll 1
        for (int s = 0; s < NSTAGE; s++) {
            int b = s & 1;
            mbar_wait(mbar + b * 8, ph[b]);
            ph[b] ^= 1;
            __syncthreads();

            if (s + 1 < NSTAGE) {
                int nb = (s + 1) & 1;
                if (tid == 0) mbar_expect_tx(mbar + nb * 8, TX_BYTES);
                if (is_loader)
                    bulk_cp(r_sm + (uint32_t)nb * STG_BYTES, Rptr + (s + 1) * KCH, ROWBYTES, mbar + nb * 8);
            }

            uint32_t stg = smb + (uint32_t)b * STG_BYTES;

            #pragma unroll
            for (int kk = 0; kk < KCH / 16; kk++) {
                uint32_t koff = (uint32_t)kk * 32u;
                uint32_t a[2][4], bfr[4][4];
                #pragma unroll
                for (int mt = 0; mt < 2; mt++)
                    ldsm4(a[mt][0], a[mt][1], a[mt][2], a[mt][3], stg + a_off[mt] + koff);
                #pragma unroll
                for (int nt2 = 0; nt2 < 4; nt2++)
                    ldsm4(bfr[nt2][0], bfr[nt2][1], bfr[nt2][2], bfr[nt2][3], stg + b_off[nt2] + koff);
                #pragma unroll
                for (int mt = 0; mt < 2; mt++)
                    #pragma unroll
                    for (int nt = 0; nt < 8; nt++)
                        mma_f16(acc[mt][nt], a[mt], bfr[nt >> 1][(nt & 1) * 2], bfr[nt >> 1][(nt & 1) * 2 + 1]);
            }
        }

        // epilogue
        const float* brw = ((mode == 0) ? b1 : b2) + (size_t)e * D + n0;

        #pragma unroll
        for (int mt = 0; mt < 2; mt++) {
            #pragma unroll
            for (int rr = 0; rr < 2; rr++) {
                int m = m0 + wm + mt * 16 + rr * 8 + g;
                if (m >= ne) continue;
                size_t rowbase = ((size_t)e * CAP + m) * D + n0;
                #pragma unroll
                for (int nt = 0; nt < 8; nt++) {
                    int col = wn + nt * 8 + tg * 2;
                    float v0 = acc[mt][nt][rr * 2 + 0] + brw[col];
                    float v1 = acc[mt][nt][rr * 2 + 1] + brw[col + 1];
                    if (mode == 0) {
                        v0 = fmaxf(v0, 0.f);
                        v1 = fmaxf(v1, 0.f);
                        *(__half2*)(g_Hh + rowbase + col) = __floats2half2_rn(v0, v1);
                    } else {
                        *(float2*)(g_O + rowbase + col) = make_float2(v0, v1);
                    }
                }
            }
        }

        if (mode == 0) {
            __threadfence();            // H stores visible before readiness publish
            __syncthreads();            // all threads' stores fenced
            if (tid == 0) atomicAdd(&g_ready[e * MT_TILES + mt_i], 1);
        }
    }
}

// ---------------- combine (float4) ----------------
__global__ void combine_kernel(float* __restrict__ y, int N)
{
    int token = blockIdx.x;
    if (token >= N) return;
    int   s0 = g_slot[token * 2 + 0];
    int   s1 = g_slot[token * 2 + 1];
    float w0 = g_wgt[token * 2 + 0];
    float w1 = g_wgt[token * 2 + 1];
    const float4* o0 = (const float4*)(g_O + (size_t)s0 * D);
    const float4* o1 = (const float4*)(g_O + (size_t)s1 * D);
    float4* yr = (float4*)(y + (size_t)token * D);
    for (int i = threadIdx.x; i < D / 4; i += blockDim.x) {
        float4 a = o0[i], b = o1[i];
        float4 r;
        r.x = w0 * a.x + w1 * b.x;
        r.y = w0 * a.y + w1 * b.y;
        r.z = w0 * a.z + w1 * b.z;
        r.w = w0 * a.w + w1 * b.w;
        yr[i] = r;
    }
}

extern "C" void kernel_launch(void* const* d_in, const int* in_sizes, int n_in,
                              void* d_out, int out_size)
{
    const float* x  = (const float*)d_in[0];
    const float* gW = (const float*)d_in[1];
    const float* gb = (const float*)d_in[2];
    const float* w1 = (const float*)d_in[3];
    const float* b1 = (const float*)d_in[4];
    const float* w2 = (const float*)d_in[5];
    const float* b2 = (const float*)d_in[6];

    int N = in_sizes[0] / D;   // 4096

    float* y         = (float*)d_out;
    float* gate_prob = (float*)d_out + (size_t)N * D;

    static int sm_count = 0;
    if (!sm_count) {
        cudaDeviceGetAttribute(&sm_count, cudaDevAttrMultiProcessorCount, 0);
        if (sm_count <= 0) sm_count = 148;
        cudaFuncSetAttribute(expert_gemm_persistent,
                             cudaFuncAttributeMaxDynamicSharedMemorySize, SMEM_BYTES);
    }

    zero_counts_kernel<<<1, 32>>>();
    convert_w_kernel<<<1184, 256>>>(w1, w2);
    gate_kernel<<<N, 256>>>(x, gW, gb, gate_prob, N);

    expert_gemm_persistent<<<sm_count, 512, SMEM_BYTES>>>(b1, b2);

    combine_kernel<<<N, 256>>>(y, N);
}